// round 1
// baseline (speedup 1.0000x reference)
#include <cuda_runtime.h>
#include <math.h>

#define BB   32
#define SS   64
#define TT   64
#define EE   256
#define HH   512
#define DD   512
#define KKQ  64
#define VOC  32000
#define G3   1536   // 3*H == 3*D

// ---------------- scratch layout (single __device__ array, no allocs) ----------------
#define NF_EMB   (BB*SS*EE)        // 524288
#define NF_GI    (BB*SS*G3)        // 3145728 (x2: fwd/bwd)
#define NF_WR    (BB*SS*2*HH)      // 2097152
#define NF_HENC  (2*BB*2*HH)       // 65536 (double buffer)
#define NF_K     (BB*SS*KKQ)       // 131072
#define NF_V     (BB*SS*DD)        // 1048576
#define NF_DEMB  (BB*(TT-1)*EE)    // 516096
#define NF_GID   (BB*(TT-1)*G3)    // 3096576
#define NF_HDEC  (BB*DD)
#define NF_HGRU  (BB*DD)
#define NF_HID   (BB*(TT-1)*DD)    // 1032192
#define NF_X     (BB*(TT-1)*DD)

#define NF_TOTAL (NF_EMB + 2*NF_GI + NF_WR + NF_HENC + NF_K + NF_V + NF_DEMB + NF_GID + NF_HDEC + NF_HGRU + NF_HID + NF_X)

__device__ float g_scr[NF_TOTAL];

__device__ __forceinline__ float sigm(float x) { return 1.0f / (1.0f + expf(-x)); }
__device__ __forceinline__ float gelu_f(float x) { return 0.5f * x * (1.0f + erff(x * 0.7071067811865475f)); }

// ---------------- init: zero henc buffers and out[:,0,:] ----------------
__global__ void init_zero(float* __restrict__ out, float* __restrict__ henc) {
    int i = blockIdx.x * blockDim.x + threadIdx.x;
    if (i < BB * VOC) {
        int b = i / VOC;
        out[(size_t)b * TT * VOC + (i % VOC)] = 0.0f;
    }
    if (i < NF_HENC) henc[i] = 0.0f;
}

// ---------------- embedding gathers ----------------
__global__ void gather_src(const int* __restrict__ src, const float* __restrict__ tab,
                           float* __restrict__ emb) {
    int i = blockIdx.x * blockDim.x + threadIdx.x;      // over B*S*(E/4)
    if (i >= BB * SS * (EE / 4)) return;
    int row = i / (EE / 4);
    int c   = i % (EE / 4);
    ((float4*)emb)[row * (EE / 4) + c] =
        ((const float4*)tab)[(size_t)src[row] * (EE / 4) + c];
}

// decoder input embeddings, rows m = t*B + b for t in [0,T-2]
__global__ void gather_trg(const int* __restrict__ trg, const float* __restrict__ tab,
                           float* __restrict__ demb) {
    int i = blockIdx.x * blockDim.x + threadIdx.x;      // over 2016*(E/4)
    if (i >= BB * (TT - 1) * (EE / 4)) return;
    int m = i / (EE / 4);
    int c = i % (EE / 4);
    int t = m / BB, b = m % BB;
    int tok = trg[b * TT + t];
    ((float4*)demb)[m * (EE / 4) + c] =
        ((const float4*)tab)[(size_t)tok * (EE / 4) + c];
}

// ---------------- generic fp32 GEMM: C = act(A[M,K] @ B[K,N] + bias) ----------------
// 64x64 block tile, BK=16, 256 threads, 4x4 per thread.
// REMAP: output row m=t*32+b -> row b*64 + t + 1 (decoder logits placement)
template<int GELU, int REMAP>
__global__ void gemm_k(const float* __restrict__ A, const float* __restrict__ Bm,
                       const float* __restrict__ bias, float* __restrict__ C,
                       int M, int N, int K) {
    __shared__ float As[16][68];
    __shared__ float Bs[16][68];
    int tid = threadIdx.x;
    int m0 = blockIdx.y * 64, n0 = blockIdx.x * 64;
    int tx = tid & 15, ty = tid >> 4;

    float acc[4][4];
#pragma unroll
    for (int i = 0; i < 4; i++)
#pragma unroll
        for (int j = 0; j < 4; j++) acc[i][j] = 0.0f;

    int lam = tid >> 2;            // 0..63  (A tile row)
    int lak = (tid & 3) * 4;       // 0,4,8,12
    int lbk = tid >> 4;            // 0..15  (B tile row)
    int lbn = (tid & 15) * 4;

    for (int k0 = 0; k0 < K; k0 += 16) {
        float4 av = (m0 + lam < M)
            ? *(const float4*)&A[(size_t)(m0 + lam) * K + k0 + lak]
            : make_float4(0.f, 0.f, 0.f, 0.f);
        float4 bv = *(const float4*)&Bm[(size_t)(k0 + lbk) * N + n0 + lbn];
        __syncthreads();
        As[lak + 0][lam] = av.x;
        As[lak + 1][lam] = av.y;
        As[lak + 2][lam] = av.z;
        As[lak + 3][lam] = av.w;
        *(float4*)&Bs[lbk][lbn] = bv;
        __syncthreads();
#pragma unroll
        for (int kk = 0; kk < 16; kk++) {
            float4 a4 = *(const float4*)&As[kk][ty * 4];
            float4 b4 = *(const float4*)&Bs[kk][tx * 4];
            float a[4] = {a4.x, a4.y, a4.z, a4.w};
            float b[4] = {b4.x, b4.y, b4.z, b4.w};
#pragma unroll
            for (int i = 0; i < 4; i++)
#pragma unroll
                for (int j = 0; j < 4; j++) acc[i][j] = fmaf(a[i], b[j], acc[i][j]);
        }
    }

#pragma unroll
    for (int i = 0; i < 4; i++) {
        int m = m0 + ty * 4 + i;
        if (m >= M) continue;
        int row = REMAP ? ((m & 31) * TT + (m >> 5) + 1) : m;
#pragma unroll
        for (int j = 0; j < 4; j++) {
            int n = n0 + tx * 4 + j;
            float v = acc[i][j] + bias[n];
            if (GELU) v = gelu_f(v);
            C[(size_t)row * N + n] = v;
        }
    }
}

// ---------------- encoder GRU step (both directions fused) ----------------
// grid (8 jtiles, 2 dirs), 256 threads. One launch per timestep.
// gh = h @ Wh ; gates fused ; masked update ; writes word_reps + h (double-buffered).
__global__ void enc_step(const float* __restrict__ Wh_f, const float* __restrict__ bh_f,
                         const float* __restrict__ Wh_b, const float* __restrict__ bh_b,
                         const int* __restrict__ src_lens,
                         const float* __restrict__ gi_f, const float* __restrict__ gi_b,
                         float* __restrict__ henc, float* __restrict__ wr_out, int step) {
    int dir = blockIdx.y;
    int t = dir ? (SS - 1 - step) : step;
    int p = step & 1;
    const float* hin  = henc + p * (BB * 2 * HH);
    float*       hout = henc + (p ^ 1) * (BB * 2 * HH);
    const float* Wh = dir ? Wh_b : Wh_f;
    const float* bh = dir ? bh_b : bh_f;
    const float* gi = dir ? gi_b : gi_f;

    int tx = threadIdx.x & 63;     // hidden-unit within tile
    int ty = threadIdx.x >> 6;     // 0..3
    int j = blockIdx.x * 64 + tx;

    __shared__ float hs[32][64];
    float ar[8], az[8], an[8];
#pragma unroll
    for (int i = 0; i < 8; i++) { ar[i] = 0.f; az[i] = 0.f; an[i] = 0.f; }

    for (int k0 = 0; k0 < HH; k0 += 64) {
        __syncthreads();
#pragma unroll
        for (int u = 0; u < 8; u++) {
            int li = threadIdx.x + u * 256;
            int bbx = li >> 6, kk = li & 63;
            hs[bbx][kk] = hin[bbx * (2 * HH) + dir * HH + k0 + kk];
        }
        __syncthreads();
#pragma unroll 8
        for (int kk = 0; kk < 64; kk++) {
            int k = k0 + kk;
            float wr = Wh[k * G3 + j];
            float wz = Wh[k * G3 + HH + j];
            float wn = Wh[k * G3 + 2 * HH + j];
#pragma unroll
            for (int i = 0; i < 8; i++) {
                float hv = hs[i * 4 + ty][kk];
                ar[i] = fmaf(hv, wr, ar[i]);
                az[i] = fmaf(hv, wz, az[i]);
                an[i] = fmaf(hv, wn, an[i]);
            }
        }
    }
    float br = bh[j], bz = bh[HH + j], bn = bh[2 * HH + j];
#pragma unroll
    for (int i = 0; i < 8; i++) {
        int b = i * 4 + ty;
        int row = b * SS + t;
        float gir = gi[(size_t)row * G3 + j];
        float giz = gi[(size_t)row * G3 + HH + j];
        float gin = gi[(size_t)row * G3 + 2 * HH + j];
        float hold = hin[b * (2 * HH) + dir * HH + j];
        float r = sigm(gir + ar[i] + br);
        float z = sigm(giz + az[i] + bz);
        float n = tanhf(gin + r * (an[i] + bn));
        float hnew = (1.0f - z) * n + z * hold;
        int len = max(src_lens[b], 1);
        bool valid = t < len;
        hout[b * (2 * HH) + dir * HH + j] = valid ? hnew : hold;
        wr_out[(size_t)(b * SS + t) * (2 * HH) + dir * HH + j] = valid ? hnew : 0.0f;
    }
}

// ---------------- decoder GRU step (no mask) ----------------
__global__ void dec_gru(const float* __restrict__ Wh, const float* __restrict__ bh,
                        const float* __restrict__ gi, const float* __restrict__ hin,
                        float* __restrict__ hout, int t) {
    int tx = threadIdx.x & 63;
    int ty = threadIdx.x >> 6;
    int j = blockIdx.x * 64 + tx;

    __shared__ float hs[32][64];
    float ar[8], az[8], an[8];
#pragma unroll
    for (int i = 0; i < 8; i++) { ar[i] = 0.f; az[i] = 0.f; an[i] = 0.f; }

    for (int k0 = 0; k0 < DD; k0 += 64) {
        __syncthreads();
#pragma unroll
        for (int u = 0; u < 8; u++) {
            int li = threadIdx.x + u * 256;
            int bbx = li >> 6, kk = li & 63;
            hs[bbx][kk] = hin[bbx * DD + k0 + kk];
        }
        __syncthreads();
#pragma unroll 8
        for (int kk = 0; kk < 64; kk++) {
            int k = k0 + kk;
            float wr = Wh[k * G3 + j];
            float wz = Wh[k * G3 + DD + j];
            float wn = Wh[k * G3 + 2 * DD + j];
#pragma unroll
            for (int i = 0; i < 8; i++) {
                float hv = hs[i * 4 + ty][kk];
                ar[i] = fmaf(hv, wr, ar[i]);
                az[i] = fmaf(hv, wz, az[i]);
                an[i] = fmaf(hv, wn, an[i]);
            }
        }
    }
    float br = bh[j], bz = bh[DD + j], bn = bh[2 * DD + j];
#pragma unroll
    for (int i = 0; i < 8; i++) {
        int b = i * 4 + ty;
        int row = t * BB + b;
        float gir = gi[(size_t)row * G3 + j];
        float giz = gi[(size_t)row * G3 + DD + j];
        float gin = gi[(size_t)row * G3 + 2 * DD + j];
        float hold = hin[b * DD + j];
        float r = sigm(gir + ar[i] + br);
        float z = sigm(giz + az[i] + bz);
        float n = tanhf(gin + r * (an[i] + bn));
        hout[b * DD + j] = (1.0f - z) * n + z * hold;
    }
}

// ---------------- decoder attention + carry update ----------------
// one block per batch element. hid = h + attn(softmax(q·K*scale), V); carry <- hid.
__global__ void dec_attn(const float* __restrict__ Wq, const float* __restrict__ bq,
                         const float* __restrict__ Kmat, const float* __restrict__ Vmat,
                         const float* __restrict__ hgru, float* __restrict__ hdec,
                         float* __restrict__ hid_all, int t) {
    int b = blockIdx.x;
    int tid = threadIdx.x;
    __shared__ float hsh[DD];
    __shared__ float qsh[KKQ];
    __shared__ float ssh[SS];
    __shared__ float red[256];

    for (int i = tid; i < DD; i += 256) hsh[i] = hgru[b * DD + i];
    __syncthreads();

    // q = h @ Wq + bq, folded scale = 1/sqrt(64)
    {
        int jq = tid & 63, part = tid >> 6;
        float acc = 0.f;
        int kb = part * 128;
        for (int k = kb; k < kb + 128; k++) acc = fmaf(hsh[k], Wq[k * KKQ + jq], acc);
        red[tid] = acc;
    }
    __syncthreads();
    if (tid < KKQ) {
        float q = red[tid] + red[tid + 64] + red[tid + 128] + red[tid + 192] + bq[tid];
        qsh[tid] = q * 0.125f;
    }
    __syncthreads();

    // scores
    if (tid < SS) {
        const float* Kp = Kmat + (size_t)(b * SS + tid) * KKQ;
        float sc = 0.f;
        for (int k = 0; k < KKQ; k++) sc = fmaf(qsh[k], Kp[k], sc);
        ssh[tid] = sc;
    }
    __syncthreads();

    // softmax over S=64
    if (tid == 0) {
        float m = ssh[0];
        for (int s = 1; s < SS; s++) m = fmaxf(m, ssh[s]);
        float sum = 0.f;
        for (int s = 0; s < SS; s++) { float e = expf(ssh[s] - m); ssh[s] = e; sum += e; }
        red[0] = 1.0f / sum;
    }
    __syncthreads();
    float inv = red[0];
    __syncthreads();
    if (tid < SS) ssh[tid] *= inv;
    __syncthreads();

    // attn + hid
    for (int d0 = tid; d0 < DD; d0 += 256) {
        float a = 0.f;
        for (int s = 0; s < SS; s++)
            a = fmaf(ssh[s], Vmat[(size_t)(b * SS + s) * DD + d0], a);
        float hid = hsh[d0] + a;
        hdec[b * DD + d0] = hid;
        hid_all[(size_t)(t * BB + b) * DD + d0] = hid;
    }
}

// ================================ host ================================
extern "C" void kernel_launch(void* const* d_in, const int* in_sizes, int n_in,
                              void* d_out, int out_size) {
    const int*   src       = (const int*)  d_in[0];
    const int*   trg       = (const int*)  d_in[1];
    const int*   src_lens  = (const int*)  d_in[2];
    const float* enc_embed = (const float*)d_in[3];
    const float* Wi_f      = (const float*)d_in[4];
    const float* Wh_f      = (const float*)d_in[5];
    const float* bi_f      = (const float*)d_in[6];
    const float* bh_f      = (const float*)d_in[7];
    const float* Wi_b      = (const float*)d_in[8];
    const float* Wh_b      = (const float*)d_in[9];
    const float* bi_b      = (const float*)d_in[10];
    const float* bh_b      = (const float*)d_in[11];
    const float* W_e2d     = (const float*)d_in[12];
    const float* b_e2d     = (const float*)d_in[13];
    const float* dec_embed = (const float*)d_in[14];
    const float* Wi_d      = (const float*)d_in[15];
    const float* Wh_d      = (const float*)d_in[16];
    const float* bi_d      = (const float*)d_in[17];
    const float* bh_d      = (const float*)d_in[18];
    const float* Wq        = (const float*)d_in[19];
    const float* bq        = (const float*)d_in[20];
    const float* Wk        = (const float*)d_in[21];
    const float* bk        = (const float*)d_in[22];
    const float* Wv        = (const float*)d_in[23];
    const float* bv        = (const float*)d_in[24];
    const float* W1        = (const float*)d_in[25];
    const float* b1        = (const float*)d_in[26];
    const float* W2        = (const float*)d_in[27];
    const float* b2        = (const float*)d_in[28];
    float* out = (float*)d_out;

    float* scr = nullptr;
    cudaGetSymbolAddress((void**)&scr, g_scr);

    float* p_emb  = scr;                    // NF_EMB
    float* p_gif  = p_emb  + NF_EMB;        // NF_GI
    float* p_gib  = p_gif  + NF_GI;         // NF_GI
    float* p_wr   = p_gib  + NF_GI;         // NF_WR
    float* p_henc = p_wr   + NF_WR;         // NF_HENC (double buffer)
    float* p_K    = p_henc + NF_HENC;       // NF_K
    float* p_V    = p_K    + NF_K;          // NF_V
    float* p_demb = p_V    + NF_V;          // NF_DEMB
    float* p_gid  = p_demb + NF_DEMB;       // NF_GID
    float* p_hdec = p_gid  + NF_GID;        // NF_HDEC
    float* p_hgru = p_hdec + NF_HDEC;       // NF_HGRU
    float* p_hid  = p_hgru + NF_HGRU;       // NF_HID
    float* p_X    = p_hid  + NF_HID;        // NF_X

    // 0) zero initial encoder state + out[:,0,:]
    init_zero<<<(BB * VOC + 255) / 256, 256>>>(out, p_henc);

    // 1) encoder input embeddings + input projections (batched over all timesteps)
    gather_src<<<(BB * SS * (EE / 4) + 255) / 256, 256>>>(src, enc_embed, p_emb);
    gemm_k<0,0><<<dim3(G3 / 64, (BB * SS) / 64), 256>>>(p_emb, Wi_f, bi_f, p_gif, BB * SS, G3, EE);
    gemm_k<0,0><<<dim3(G3 / 64, (BB * SS) / 64), 256>>>(p_emb, Wi_b, bi_b, p_gib, BB * SS, G3, EE);

    // 2) encoder recurrence: one launch per step, fwd+bwd fused
    for (int step = 0; step < SS; step++) {
        enc_step<<<dim3(HH / 64, 2), 256>>>(Wh_f, bh_f, Wh_b, bh_b, src_lens,
                                            p_gif, p_gib, p_henc, p_wr, step);
    }
    // final hidden states land in buffer 0 (64 steps -> even parity)
    float* p_sent = p_henc;

    // 3) K, V projections and decoder initial state
    gemm_k<0,0><<<dim3(KKQ / 64, (BB * SS) / 64), 256>>>(p_wr, Wk, bk, p_K, BB * SS, KKQ, 2 * HH);
    gemm_k<0,0><<<dim3(DD / 64, (BB * SS) / 64), 256>>>(p_wr, Wv, bv, p_V, BB * SS, DD, 2 * HH);
    gemm_k<1,0><<<dim3(DD / 64, 1), 256>>>(p_sent, W_e2d, b_e2d, p_hdec, BB, DD, 2 * HH);

    // 4) decoder input embeddings + input projections (batched)
    gather_trg<<<(BB * (TT - 1) * (EE / 4) + 255) / 256, 256>>>(trg, dec_embed, p_demb);
    gemm_k<0,0><<<dim3(G3 / 64, (BB * (TT - 1) + 63) / 64), 256>>>(p_demb, Wi_d, bi_d, p_gid,
                                                                   BB * (TT - 1), G3, EE);

    // 5) decoder recurrence: GRU + attention per step; store hid for batched head
    for (int t = 0; t < TT - 1; t++) {
        dec_gru<<<DD / 64, 256>>>(Wh_d, bh_d, p_gid, p_hdec, p_hgru, t);
        dec_attn<<<BB, 256>>>(Wq, bq, p_K, p_V, p_hgru, p_hdec, p_hid, t);
    }

    // 6) output head, batched over all (t, b): X = gelu(hid @ W1 + b1); out = X @ W2 + b2
    gemm_k<1,0><<<dim3(DD / 64, (BB * (TT - 1) + 63) / 64), 256>>>(p_hid, W1, b1, p_X,
                                                                   BB * (TT - 1), DD, DD);
    gemm_k<0,1><<<dim3(VOC / 64, (BB * (TT - 1) + 63) / 64), 256>>>(p_X, W2, b2, out,
                                                                    BB * (TT - 1), VOC, DD);
}

// round 4
// speedup vs baseline: 1.1620x; 1.1620x over previous
#include <cuda_runtime.h>
#include <cuda_fp16.h>
#include <cstdint>
#include <math.h>

#define BB   32
#define SS   64
#define TT   64
#define EE   256
#define HH   512
#define DD   512
#define KKQ  64
#define VOC  32000
#define G3   1536   // 3*H == 3*D
#define MROWS (BB*(TT-1))   // 2016

// ---------------- scratch layout (single __device__ array, no allocs) ----------------
#define NF_EMB   (BB*SS*EE)
#define NF_GI    (BB*SS*G3)
#define NF_WR    (BB*SS*2*HH)
#define NF_HENC  (2*BB*2*HH)
#define NF_K     (BB*SS*KKQ)
#define NF_V     (BB*SS*DD)
#define NF_DEMB  (BB*(TT-1)*EE)
#define NF_GID   (BB*(TT-1)*G3)
#define NF_HDEC  (BB*DD)
#define NF_HGRU  (BB*DD)
#define NF_HID   (BB*(TT-1)*DD)
#define NF_X     (BB*(TT-1)*DD)

#define NF_TOTAL (NF_EMB + 2*NF_GI + NF_WR + NF_HENC + NF_K + NF_V + NF_DEMB + NF_GID + NF_HDEC + NF_HGRU + NF_HID + NF_X)

__device__ float g_scr[NF_TOTAL];
__device__ __half g_xh[MROWS * DD];          // fp16 copy of gelu(hid@W1+b1)
__device__ __half g_w2h[VOC * DD];           // W2 transposed to [N,K] fp16

__device__ __forceinline__ float sigm(float x) { return 1.0f / (1.0f + expf(-x)); }
__device__ __forceinline__ float gelu_f(float x) { return 0.5f * x * (1.0f + erff(x * 0.7071067811865475f)); }

// ---------------- init ----------------
__global__ void init_zero(float* __restrict__ out, float* __restrict__ henc) {
    int i = blockIdx.x * blockDim.x + threadIdx.x;
    if (i < BB * VOC) {
        int b = i / VOC;
        out[(size_t)b * TT * VOC + (i % VOC)] = 0.0f;
    }
    if (i < NF_HENC) henc[i] = 0.0f;
}

// ---------------- embedding gathers ----------------
__global__ void gather_src(const int* __restrict__ src, const float* __restrict__ tab,
                           float* __restrict__ emb) {
    int i = blockIdx.x * blockDim.x + threadIdx.x;
    if (i >= BB * SS * (EE / 4)) return;
    int row = i / (EE / 4);
    int c   = i % (EE / 4);
    ((float4*)emb)[row * (EE / 4) + c] =
        ((const float4*)tab)[(size_t)src[row] * (EE / 4) + c];
}

__global__ void gather_trg(const int* __restrict__ trg, const float* __restrict__ tab,
                           float* __restrict__ demb) {
    int i = blockIdx.x * blockDim.x + threadIdx.x;
    if (i >= BB * (TT - 1) * (EE / 4)) return;
    int m = i / (EE / 4);
    int c = i % (EE / 4);
    int t = m / BB, b = m % BB;
    int tok = trg[b * TT + t];
    ((float4*)demb)[m * (EE / 4) + c] =
        ((const float4*)tab)[(size_t)tok * (EE / 4) + c];
}

// ---------------- generic fp32 GEMM: C = act(A[M,K] @ B[K,N] + bias) ----------------
template<int GELU>
__global__ void gemm_k(const float* __restrict__ A, const float* __restrict__ Bm,
                       const float* __restrict__ bias, float* __restrict__ C,
                       int M, int N, int K) {
    __shared__ float As[16][68];
    __shared__ float Bs[16][68];
    int tid = threadIdx.x;
    int m0 = blockIdx.y * 64, n0 = blockIdx.x * 64;
    int tx = tid & 15, ty = tid >> 4;

    float acc[4][4];
#pragma unroll
    for (int i = 0; i < 4; i++)
#pragma unroll
        for (int j = 0; j < 4; j++) acc[i][j] = 0.0f;

    int lam = tid >> 2;
    int lak = (tid & 3) * 4;
    int lbk = tid >> 4;
    int lbn = (tid & 15) * 4;

    for (int k0 = 0; k0 < K; k0 += 16) {
        float4 av = (m0 + lam < M)
            ? *(const float4*)&A[(size_t)(m0 + lam) * K + k0 + lak]
            : make_float4(0.f, 0.f, 0.f, 0.f);
        float4 bv = *(const float4*)&Bm[(size_t)(k0 + lbk) * N + n0 + lbn];
        __syncthreads();
        As[lak + 0][lam] = av.x;
        As[lak + 1][lam] = av.y;
        As[lak + 2][lam] = av.z;
        As[lak + 3][lam] = av.w;
        *(float4*)&Bs[lbk][lbn] = bv;
        __syncthreads();
#pragma unroll
        for (int kk = 0; kk < 16; kk++) {
            float4 a4 = *(const float4*)&As[kk][ty * 4];
            float4 b4 = *(const float4*)&Bs[kk][tx * 4];
            float a[4] = {a4.x, a4.y, a4.z, a4.w};
            float b[4] = {b4.x, b4.y, b4.z, b4.w};
#pragma unroll
            for (int i = 0; i < 4; i++)
#pragma unroll
                for (int j = 0; j < 4; j++) acc[i][j] = fmaf(a[i], b[j], acc[i][j]);
        }
    }

#pragma unroll
    for (int i = 0; i < 4; i++) {
        int m = m0 + ty * 4 + i;
        if (m >= M) continue;
#pragma unroll
        for (int j = 0; j < 4; j++) {
            int n = n0 + tx * 4 + j;
            float v = acc[i][j] + bias[n];
            if (GELU) v = gelu_f(v);
            C[(size_t)m * N + n] = v;
        }
    }
}

// ---------------- encoder GRU step (both directions fused) ----------------
__global__ void enc_step(const float* __restrict__ Wh_f, const float* __restrict__ bh_f,
                         const float* __restrict__ Wh_b, const float* __restrict__ bh_b,
                         const int* __restrict__ src_lens,
                         const float* __restrict__ gi_f, const float* __restrict__ gi_b,
                         float* __restrict__ henc, float* __restrict__ wr_out, int step) {
    int dir = blockIdx.y;
    int t = dir ? (SS - 1 - step) : step;
    int p = step & 1;
    const float* hin  = henc + p * (BB * 2 * HH);
    float*       hout = henc + (p ^ 1) * (BB * 2 * HH);
    const float* Wh = dir ? Wh_b : Wh_f;
    const float* bh = dir ? bh_b : bh_f;
    const float* gi = dir ? gi_b : gi_f;

    int tx = threadIdx.x & 63;
    int ty = threadIdx.x >> 6;
    int j = blockIdx.x * 64 + tx;

    __shared__ float hs[32][64];
    float ar[8], az[8], an[8];
#pragma unroll
    for (int i = 0; i < 8; i++) { ar[i] = 0.f; az[i] = 0.f; an[i] = 0.f; }

    for (int k0 = 0; k0 < HH; k0 += 64) {
        __syncthreads();
#pragma unroll
        for (int u = 0; u < 8; u++) {
            int li = threadIdx.x + u * 256;
            int bbx = li >> 6, kk = li & 63;
            hs[bbx][kk] = hin[bbx * (2 * HH) + dir * HH + k0 + kk];
        }
        __syncthreads();
#pragma unroll 8
        for (int kk = 0; kk < 64; kk++) {
            int k = k0 + kk;
            float wr = Wh[k * G3 + j];
            float wz = Wh[k * G3 + HH + j];
            float wn = Wh[k * G3 + 2 * HH + j];
#pragma unroll
            for (int i = 0; i < 8; i++) {
                float hv = hs[i * 4 + ty][kk];
                ar[i] = fmaf(hv, wr, ar[i]);
                az[i] = fmaf(hv, wz, az[i]);
                an[i] = fmaf(hv, wn, an[i]);
            }
        }
    }
    float br = bh[j], bz = bh[HH + j], bn = bh[2 * HH + j];
#pragma unroll
    for (int i = 0; i < 8; i++) {
        int b = i * 4 + ty;
        int row = b * SS + t;
        float gir = gi[(size_t)row * G3 + j];
        float giz = gi[(size_t)row * G3 + HH + j];
        float gin = gi[(size_t)row * G3 + 2 * HH + j];
        float hold = hin[b * (2 * HH) + dir * HH + j];
        float r = sigm(gir + ar[i] + br);
        float z = sigm(giz + az[i] + bz);
        float n = tanhf(gin + r * (an[i] + bn));
        float hnew = (1.0f - z) * n + z * hold;
        int len = max(src_lens[b], 1);
        bool valid = t < len;
        hout[b * (2 * HH) + dir * HH + j] = valid ? hnew : hold;
        wr_out[(size_t)(b * SS + t) * (2 * HH) + dir * HH + j] = valid ? hnew : 0.0f;
    }
}

// ---------------- decoder GRU step ----------------
__global__ void dec_gru(const float* __restrict__ Wh, const float* __restrict__ bh,
                        const float* __restrict__ gi, const float* __restrict__ hin,
                        float* __restrict__ hout, int t) {
    int tx = threadIdx.x & 63;
    int ty = threadIdx.x >> 6;
    int j = blockIdx.x * 64 + tx;

    __shared__ float hs[32][64];
    float ar[8], az[8], an[8];
#pragma unroll
    for (int i = 0; i < 8; i++) { ar[i] = 0.f; az[i] = 0.f; an[i] = 0.f; }

    for (int k0 = 0; k0 < DD; k0 += 64) {
        __syncthreads();
#pragma unroll
        for (int u = 0; u < 8; u++) {
            int li = threadIdx.x + u * 256;
            int bbx = li >> 6, kk = li & 63;
            hs[bbx][kk] = hin[bbx * DD + k0 + kk];
        }
        __syncthreads();
#pragma unroll 8
        for (int kk = 0; kk < 64; kk++) {
            int k = k0 + kk;
            float wr = Wh[k * G3 + j];
            float wz = Wh[k * G3 + DD + j];
            float wn = Wh[k * G3 + 2 * DD + j];
#pragma unroll
            for (int i = 0; i < 8; i++) {
                float hv = hs[i * 4 + ty][kk];
                ar[i] = fmaf(hv, wr, ar[i]);
                az[i] = fmaf(hv, wz, az[i]);
                an[i] = fmaf(hv, wn, an[i]);
            }
        }
    }
    float br = bh[j], bz = bh[DD + j], bn = bh[2 * DD + j];
#pragma unroll
    for (int i = 0; i < 8; i++) {
        int b = i * 4 + ty;
        int row = t * BB + b;
        float gir = gi[(size_t)row * G3 + j];
        float giz = gi[(size_t)row * G3 + DD + j];
        float gin = gi[(size_t)row * G3 + 2 * DD + j];
        float hold = hin[b * DD + j];
        float r = sigm(gir + ar[i] + br);
        float z = sigm(giz + az[i] + bz);
        float n = tanhf(gin + r * (an[i] + bn));
        hout[b * DD + j] = (1.0f - z) * n + z * hold;
    }
}

// ---------------- decoder attention + carry update ----------------
__global__ void dec_attn(const float* __restrict__ Wq, const float* __restrict__ bq,
                         const float* __restrict__ Kmat, const float* __restrict__ Vmat,
                         const float* __restrict__ hgru, float* __restrict__ hdec,
                         float* __restrict__ hid_all, int t) {
    int b = blockIdx.x;
    int tid = threadIdx.x;
    __shared__ float hsh[DD];
    __shared__ float qsh[KKQ];
    __shared__ float ssh[SS];
    __shared__ float red[256];

    for (int i = tid; i < DD; i += 256) hsh[i] = hgru[b * DD + i];
    __syncthreads();

    {
        int jq = tid & 63, part = tid >> 6;
        float acc = 0.f;
        int kb = part * 128;
        for (int k = kb; k < kb + 128; k++) acc = fmaf(hsh[k], Wq[k * KKQ + jq], acc);
        red[tid] = acc;
    }
    __syncthreads();
    if (tid < KKQ) {
        float q = red[tid] + red[tid + 64] + red[tid + 128] + red[tid + 192] + bq[tid];
        qsh[tid] = q * 0.125f;
    }
    __syncthreads();

    if (tid < SS) {
        const float* Kp = Kmat + (size_t)(b * SS + tid) * KKQ;
        float sc = 0.f;
        for (int k = 0; k < KKQ; k++) sc = fmaf(qsh[k], Kp[k], sc);
        ssh[tid] = sc;
    }
    __syncthreads();

    if (tid == 0) {
        float m = ssh[0];
        for (int s = 1; s < SS; s++) m = fmaxf(m, ssh[s]);
        float sum = 0.f;
        for (int s = 0; s < SS; s++) { float e = expf(ssh[s] - m); ssh[s] = e; sum += e; }
        red[0] = 1.0f / sum;
    }
    __syncthreads();
    float inv = red[0];
    __syncthreads();
    if (tid < SS) ssh[tid] *= inv;
    __syncthreads();

    for (int d0 = tid; d0 < DD; d0 += 256) {
        float a = 0.f;
        for (int s = 0; s < SS; s++)
            a = fmaf(ssh[s], Vmat[(size_t)(b * SS + s) * DD + d0], a);
        float hid = hsh[d0] + a;
        hdec[b * DD + d0] = hid;
        hid_all[(size_t)(t * BB + b) * DD + d0] = hid;
    }
}

// ---------------- fp32 -> fp16 conversions ----------------
__global__ void convert_x(const float* __restrict__ X, __half* __restrict__ Xh) {
    int i = blockIdx.x * blockDim.x + threadIdx.x;   // over MROWS*DD/4
    if (i >= MROWS * DD / 4) return;
    float4 v = ((const float4*)X)[i];
    __half2 a = __floats2half2_rn(v.x, v.y);
    __half2 b = __floats2half2_rn(v.z, v.w);
    uint2 pk;
    pk.x = *(uint32_t*)&a;
    pk.y = *(uint32_t*)&b;
    ((uint2*)Xh)[i] = pk;
}

// transpose W2 [K=512, N=32000] fp32 -> W2h [N, K] fp16
__global__ void transpose_w2(const float* __restrict__ W2, __half* __restrict__ W2h) {
    __shared__ float ts[32][33];
    int n0 = blockIdx.x * 32;
    int k0 = blockIdx.y * 32;
    int tx = threadIdx.x, ty = threadIdx.y;
#pragma unroll
    for (int j = 0; j < 4; j++)
        ts[ty + j * 8][tx] = W2[(size_t)(k0 + ty + j * 8) * VOC + n0 + tx];
    __syncthreads();
#pragma unroll
    for (int j = 0; j < 4; j++) {
        int n = n0 + ty + j * 8;
        int k = k0 + tx;
        W2h[(size_t)n * DD + k] = __float2half(ts[tx][ty + j * 8]);
    }
}

// ================= HMMA fp16 head GEMM: out = Xh @ W2h^T + b2 (remapped) =================
// mma.sync.m16n8k16 (sm_80+ base target, no 'a' features).
// CTA tile 128(M) x 128(N); 8 warps 2x4; warp tile 64x32; K=512 in 8 chunks of 64.

#define HPITCH 72   // smem row pitch in halfs (144B -> conflict-free ldmatrix)

__device__ __forceinline__ uint32_t smem_u32(const void* p) {
    uint32_t a;
    asm("{ .reg .u64 t; cvta.to.shared.u64 t, %1; cvt.u32.u64 %0, t; }" : "=r"(a) : "l"(p));
    return a;
}

__device__ __forceinline__ void ldmatrix_x4(uint32_t* r, uint32_t addr) {
    asm volatile("ldmatrix.sync.aligned.m8n8.x4.shared.b16 {%0,%1,%2,%3}, [%4];"
                 : "=r"(r[0]), "=r"(r[1]), "=r"(r[2]), "=r"(r[3]) : "r"(addr));
}
__device__ __forceinline__ void ldmatrix_x2(uint32_t* r, uint32_t addr) {
    asm volatile("ldmatrix.sync.aligned.m8n8.x2.shared.b16 {%0,%1}, [%2];"
                 : "=r"(r[0]), "=r"(r[1]) : "r"(addr));
}
__device__ __forceinline__ void mma16816(float* c, const uint32_t* a, const uint32_t* b) {
    asm volatile(
        "mma.sync.aligned.m16n8k16.row.col.f32.f16.f16.f32 "
        "{%0,%1,%2,%3}, {%4,%5,%6,%7}, {%8,%9}, {%0,%1,%2,%3};"
        : "+f"(c[0]), "+f"(c[1]), "+f"(c[2]), "+f"(c[3])
        : "r"(a[0]), "r"(a[1]), "r"(a[2]), "r"(a[3]), "r"(b[0]), "r"(b[1]));
}

__global__ void __launch_bounds__(256, 1)
head_mma(const __half* __restrict__ Xh, const __half* __restrict__ W2h,
         const float* __restrict__ b2, float* __restrict__ out) {
    __shared__ __half As[128 * HPITCH];
    __shared__ __half Bs[128 * HPITCH];

    int tid = threadIdx.x;
    int wid = tid >> 5, lane = tid & 31;
    int m0 = blockIdx.x * 128;        // m-fast grid order: co-resident CTAs share B tile
    int n0 = blockIdx.y * 128;
    int wm = (wid >> 2) * 64;         // warp m offset within tile
    int wn = (wid & 3) * 32;          // warp n offset

    float c[4][4][4];
#pragma unroll
    for (int mi = 0; mi < 4; mi++)
#pragma unroll
        for (int ni = 0; ni < 4; ni++)
#pragma unroll
            for (int q = 0; q < 4; q++) c[mi][ni][q] = 0.0f;

    uint32_t as_base = smem_u32(As);
    uint32_t bs_base = smem_u32(Bs);

    for (int kc = 0; kc < 8; kc++) {
        int k0 = kc * 64;
        // stage A,B chunk: 128 rows x 64 halfs each; 256 thr x 8 iters x uint4
        __syncthreads();
#pragma unroll
        for (int it = 0; it < 4; it++) {
            int idx = it * 256 + tid;           // 0..1023 -> 128 rows x 8 col-groups
            int row = idx >> 3;
            int col = (idx & 7) * 8;
            uint4 va = (m0 + row < MROWS)
                ? *(const uint4*)(Xh + (size_t)(m0 + row) * DD + k0 + col)
                : make_uint4(0, 0, 0, 0);
            *(uint4*)(As + row * HPITCH + col) = va;
            uint4 vb = *(const uint4*)(W2h + (size_t)(n0 + row) * DD + k0 + col);
            *(uint4*)(Bs + row * HPITCH + col) = vb;
        }
        __syncthreads();

#pragma unroll
        for (int k16 = 0; k16 < 4; k16++) {
            uint32_t afrag[4][4], bfrag[4][2];
#pragma unroll
            for (int mi = 0; mi < 4; mi++) {
                int r = wm + mi * 16 + (lane & 15);
                int cl = k16 * 16 + ((lane >> 4) * 8);
                ldmatrix_x4(afrag[mi], as_base + (uint32_t)(r * HPITCH + cl) * 2);
            }
#pragma unroll
            for (int ni = 0; ni < 4; ni++) {
                int r = wn + ni * 8 + (lane & 7);
                int cl = k16 * 16 + (((lane >> 3) & 1) * 8);
                ldmatrix_x2(bfrag[ni], bs_base + (uint32_t)(r * HPITCH + cl) * 2);
            }
#pragma unroll
            for (int mi = 0; mi < 4; mi++)
#pragma unroll
                for (int ni = 0; ni < 4; ni++)
                    mma16816(c[mi][ni], afrag[mi], bfrag[ni]);
        }
    }

    // epilogue: each thread owns rows (lane/4, lane/4+8) cols 2*(lane%4)+{0,1} per tile
    int rbase = lane >> 2;
    int cbase = (lane & 3) * 2;
#pragma unroll
    for (int mi = 0; mi < 4; mi++) {
#pragma unroll
        for (int half2i = 0; half2i < 2; half2i++) {
            int m = m0 + wm + mi * 16 + rbase + half2i * 8;
            if (m >= MROWS) continue;
            int b = m & 31, t = m >> 5;
            float* orow = out + (size_t)(b * TT + t + 1) * VOC;
#pragma unroll
            for (int ni = 0; ni < 4; ni++) {
                int n = n0 + wn + ni * 8 + cbase;
                float2 v;
                v.x = c[mi][ni][half2i * 2 + 0] + b2[n];
                v.y = c[mi][ni][half2i * 2 + 1] + b2[n + 1];
                *(float2*)(orow + n) = v;
            }
        }
    }
}

// ================================ host ================================
extern "C" void kernel_launch(void* const* d_in, const int* in_sizes, int n_in,
                              void* d_out, int out_size) {
    const int*   src       = (const int*)  d_in[0];
    const int*   trg       = (const int*)  d_in[1];
    const int*   src_lens  = (const int*)  d_in[2];
    const float* enc_embed = (const float*)d_in[3];
    const float* Wi_f      = (const float*)d_in[4];
    const float* Wh_f      = (const float*)d_in[5];
    const float* bi_f      = (const float*)d_in[6];
    const float* bh_f      = (const float*)d_in[7];
    const float* Wi_b      = (const float*)d_in[8];
    const float* Wh_b      = (const float*)d_in[9];
    const float* bi_b      = (const float*)d_in[10];
    const float* bh_b      = (const float*)d_in[11];
    const float* W_e2d     = (const float*)d_in[12];
    const float* b_e2d     = (const float*)d_in[13];
    const float* dec_embed = (const float*)d_in[14];
    const float* Wi_d      = (const float*)d_in[15];
    const float* Wh_d      = (const float*)d_in[16];
    const float* bi_d      = (const float*)d_in[17];
    const float* bh_d      = (const float*)d_in[18];
    const float* Wq        = (const float*)d_in[19];
    const float* bq        = (const float*)d_in[20];
    const float* Wk        = (const float*)d_in[21];
    const float* bk        = (const float*)d_in[22];
    const float* Wv        = (const float*)d_in[23];
    const float* bv        = (const float*)d_in[24];
    const float* W1        = (const float*)d_in[25];
    const float* b1        = (const float*)d_in[26];
    const float* W2        = (const float*)d_in[27];
    const float* b2        = (const float*)d_in[28];
    float* out = (float*)d_out;

    float* scr = nullptr;
    cudaGetSymbolAddress((void**)&scr, g_scr);
    __half* xh = nullptr;
    cudaGetSymbolAddress((void**)&xh, g_xh);
    __half* w2h = nullptr;
    cudaGetSymbolAddress((void**)&w2h, g_w2h);

    float* p_emb  = scr;
    float* p_gif  = p_emb  + NF_EMB;
    float* p_gib  = p_gif  + NF_GI;
    float* p_wr   = p_gib  + NF_GI;
    float* p_henc = p_wr   + NF_WR;
    float* p_K    = p_henc + NF_HENC;
    float* p_V    = p_K    + NF_K;
    float* p_demb = p_V    + NF_V;
    float* p_gid  = p_demb + NF_DEMB;
    float* p_hdec = p_gid  + NF_GID;
    float* p_hgru = p_hdec + NF_HDEC;
    float* p_hid  = p_hgru + NF_HGRU;
    float* p_X    = p_hid  + NF_HID;

    // 0) zero initial encoder state + out[:,0,:]
    init_zero<<<(BB * VOC + 255) / 256, 256>>>(out, p_henc);

    // W2 transpose+convert (independent of everything else)
    transpose_w2<<<dim3(VOC / 32, DD / 32), dim3(32, 8)>>>(W2, w2h);

    // 1) encoder input embeddings + input projections
    gather_src<<<(BB * SS * (EE / 4) + 255) / 256, 256>>>(src, enc_embed, p_emb);
    gemm_k<0><<<dim3(G3 / 64, (BB * SS) / 64), 256>>>(p_emb, Wi_f, bi_f, p_gif, BB * SS, G3, EE);
    gemm_k<0><<<dim3(G3 / 64, (BB * SS) / 64), 256>>>(p_emb, Wi_b, bi_b, p_gib, BB * SS, G3, EE);

    // 2) encoder recurrence
    for (int step = 0; step < SS; step++) {
        enc_step<<<dim3(HH / 64, 2), 256>>>(Wh_f, bh_f, Wh_b, bh_b, src_lens,
                                            p_gif, p_gib, p_henc, p_wr, step);
    }
    float* p_sent = p_henc;

    // 3) K, V projections and decoder initial state
    gemm_k<0><<<dim3(KKQ / 64, (BB * SS) / 64), 256>>>(p_wr, Wk, bk, p_K, BB * SS, KKQ, 2 * HH);
    gemm_k<0><<<dim3(DD / 64, (BB * SS) / 64), 256>>>(p_wr, Wv, bv, p_V, BB * SS, DD, 2 * HH);
    gemm_k<1><<<dim3(DD / 64, 1), 256>>>(p_sent, W_e2d, b_e2d, p_hdec, BB, DD, 2 * HH);

    // 4) decoder input embeddings + input projections
    gather_trg<<<(BB * (TT - 1) * (EE / 4) + 255) / 256, 256>>>(trg, dec_embed, p_demb);
    gemm_k<0><<<dim3(G3 / 64, (BB * (TT - 1) + 63) / 64), 256>>>(p_demb, Wi_d, bi_d, p_gid,
                                                                 BB * (TT - 1), G3, EE);

    // 5) decoder recurrence
    for (int t = 0; t < TT - 1; t++) {
        dec_gru<<<DD / 64, 256>>>(Wh_d, bh_d, p_gid, p_hdec, p_hgru, t);
        dec_attn<<<BB, 256>>>(Wq, bq, p_K, p_V, p_hgru, p_hdec, p_hid, t);
    }

    // 6) output head: X = gelu(hid @ W1 + b1) (fp32), then HMMA fp16 GEMM vs W2
    gemm_k<1><<<dim3(DD / 64, (BB * (TT - 1) + 63) / 64), 256>>>(p_hid, W1, b1, p_X,
                                                                 BB * (TT - 1), DD, DD);
    convert_x<<<(MROWS * DD / 4 + 255) / 256, 256>>>(p_X, xh);
    head_mma<<<dim3((MROWS + 127) / 128, VOC / 128), 256>>>(xh, w2h, b2, out);
}

// round 5
// speedup vs baseline: 3.3582x; 2.8901x over previous
#include <cuda_runtime.h>
#include <cuda_fp16.h>
#include <cstdint>
#include <math.h>

#define BB   32
#define SS   64
#define TT   64
#define EE   256
#define HH   512
#define DD   512
#define KKQ  64
#define VOC  32000
#define G3   1536   // 3*H == 3*D
#define MROWS (BB*(TT-1))   // 2016

// ---------------- scratch layout (single __device__ array, no allocs) ----------------
#define NF_EMB   (BB*SS*EE)
#define NF_GI    (BB*SS*G3)
#define NF_WR    (BB*SS*2*HH)
#define NF_HENC  (2*BB*2*HH)
#define NF_K     (BB*SS*KKQ)
#define NF_V     (BB*SS*DD)
#define NF_DEMB  (BB*(TT-1)*EE)
#define NF_GID   (BB*(TT-1)*G3)
#define NF_HDEC  (BB*DD)
#define NF_HGRU  (BB*DD)
#define NF_HID   (BB*(TT-1)*DD)
#define NF_X     (BB*(TT-1)*DD)
#define NF_WHPE  (2*512*512*4)
#define NF_WHPD  (512*512*4)
#define NF_PGH   (2*4*3*32*512)

#define NF_TOTAL (NF_EMB + 2*NF_GI + NF_WR + NF_HENC + NF_K + NF_V + NF_DEMB + NF_GID + \
                  NF_HDEC + NF_HGRU + NF_HID + NF_X + NF_WHPE + NF_WHPD + NF_PGH)

__device__ float g_scr[NF_TOTAL];
__device__ __half g_xh[MROWS * DD];
__device__ __half g_w2h[VOC * DD];
__device__ unsigned g_bar_enc;
__device__ unsigned g_bar_dec;

__device__ __forceinline__ float sigm(float x) { return 1.0f / (1.0f + expf(-x)); }
__device__ __forceinline__ float gelu_f(float x) { return 0.5f * x * (1.0f + erff(x * 0.7071067811865475f)); }

__device__ __forceinline__ float ldcg1(const float* p) {
    float v; asm volatile("ld.global.cg.f32 %0, [%1];" : "=f"(v) : "l"(p)); return v;
}
__device__ __forceinline__ float4 ldcg4(const float* p) {
    float4 v;
    asm volatile("ld.global.cg.v4.f32 {%0,%1,%2,%3}, [%4];"
                 : "=f"(v.x), "=f"(v.y), "=f"(v.z), "=f"(v.w) : "l"(p));
    return v;
}

// software grid barrier (all CTAs resident; counter reset per launch in init_zero)
__device__ __forceinline__ void gsync(unsigned* bar, unsigned& epoch, unsigned nb) {
    __syncthreads();
    if (threadIdx.x == 0) {
        epoch += nb;
        __threadfence();
        atomicAdd(bar, 1u);
        while (*(volatile unsigned*)bar < epoch) __nanosleep(64);
    }
    __syncthreads();
}

// ---------------- init: zero enc state, out[:,0,:], barrier counters ----------------
__global__ void init_zero(float* __restrict__ out, float* __restrict__ henc) {
    int i = blockIdx.x * blockDim.x + threadIdx.x;
    if (i == 0) { g_bar_enc = 0; g_bar_dec = 0; }
    if (i < BB * VOC) {
        int b = i / VOC;
        out[(size_t)b * TT * VOC + (i % VOC)] = 0.0f;
    }
    if (i < NF_HENC) henc[i] = 0.0f;
}

// ---------------- embedding gathers ----------------
__global__ void gather_src(const int* __restrict__ src, const float* __restrict__ tab,
                           float* __restrict__ emb) {
    int i = blockIdx.x * blockDim.x + threadIdx.x;
    if (i >= BB * SS * (EE / 4)) return;
    int row = i / (EE / 4);
    int c   = i % (EE / 4);
    ((float4*)emb)[row * (EE / 4) + c] =
        ((const float4*)tab)[(size_t)src[row] * (EE / 4) + c];
}

__global__ void gather_trg(const int* __restrict__ trg, const float* __restrict__ tab,
                           float* __restrict__ demb) {
    int i = blockIdx.x * blockDim.x + threadIdx.x;
    if (i >= BB * (TT - 1) * (EE / 4)) return;
    int m = i / (EE / 4);
    int c = i % (EE / 4);
    int t = m / BB, b = m % BB;
    int tok = trg[b * TT + t];
    ((float4*)demb)[m * (EE / 4) + c] =
        ((const float4*)tab)[(size_t)tok * (EE / 4) + c];
}

// ---------------- pack recurrent weights: float4 (wr,wz,wn,0) per (k,j) ----------------
__global__ void pack_wh(const float* __restrict__ Wh_f, const float* __restrict__ Wh_b,
                        const float* __restrict__ Wh_d,
                        float* __restrict__ whpe, float* __restrict__ whpd) {
    int idx = blockIdx.x * blockDim.x + threadIdx.x;
    if (idx >= 512 * 512) return;
    int k = idx >> 9, j = idx & 511;
    float4 vf = make_float4(Wh_f[k * G3 + j], Wh_f[k * G3 + 512 + j], Wh_f[k * G3 + 1024 + j], 0.f);
    float4 vb = make_float4(Wh_b[k * G3 + j], Wh_b[k * G3 + 512 + j], Wh_b[k * G3 + 1024 + j], 0.f);
    float4 vd = make_float4(Wh_d[k * G3 + j], Wh_d[k * G3 + 512 + j], Wh_d[k * G3 + 1024 + j], 0.f);
    ((float4*)whpe)[idx] = vf;
    ((float4*)whpe)[512 * 512 + idx] = vb;
    ((float4*)whpd)[idx] = vd;
}

// ---------------- generic fp32 GEMM: C = act(A[M,K] @ B[K,N] + bias) ----------------
template<int GELU>
__global__ void gemm_k(const float* __restrict__ A, const float* __restrict__ Bm,
                       const float* __restrict__ bias, float* __restrict__ C,
                       int M, int N, int K) {
    __shared__ float As[16][68];
    __shared__ float Bs[16][68];
    int tid = threadIdx.x;
    int m0 = blockIdx.y * 64, n0 = blockIdx.x * 64;
    int tx = tid & 15, ty = tid >> 4;

    float acc[4][4];
#pragma unroll
    for (int i = 0; i < 4; i++)
#pragma unroll
        for (int j = 0; j < 4; j++) acc[i][j] = 0.0f;

    int lam = tid >> 2;
    int lak = (tid & 3) * 4;
    int lbk = tid >> 4;
    int lbn = (tid & 15) * 4;

    for (int k0 = 0; k0 < K; k0 += 16) {
        float4 av = (m0 + lam < M)
            ? *(const float4*)&A[(size_t)(m0 + lam) * K + k0 + lak]
            : make_float4(0.f, 0.f, 0.f, 0.f);
        float4 bv = *(const float4*)&Bm[(size_t)(k0 + lbk) * N + n0 + lbn];
        __syncthreads();
        As[lak + 0][lam] = av.x;
        As[lak + 1][lam] = av.y;
        As[lak + 2][lam] = av.z;
        As[lak + 3][lam] = av.w;
        *(float4*)&Bs[lbk][lbn] = bv;
        __syncthreads();
#pragma unroll
        for (int kk = 0; kk < 16; kk++) {
            float4 a4 = *(const float4*)&As[kk][ty * 4];
            float4 b4 = *(const float4*)&Bs[kk][tx * 4];
            float a[4] = {a4.x, a4.y, a4.z, a4.w};
            float b[4] = {b4.x, b4.y, b4.z, b4.w};
#pragma unroll
            for (int i = 0; i < 4; i++)
#pragma unroll
                for (int j = 0; j < 4; j++) acc[i][j] = fmaf(a[i], b[j], acc[i][j]);
        }
    }

#pragma unroll
    for (int i = 0; i < 4; i++) {
        int m = m0 + ty * 4 + i;
        if (m >= M) continue;
#pragma unroll
        for (int j = 0; j < 4; j++) {
            int n = n0 + tx * 4 + j;
            float v = acc[i][j] + bias[n];
            if (GELU) v = gelu_f(v);
            C[(size_t)m * N + n] = v;
        }
    }
}

// ================= persistent encoder: all 64 steps, both dirs, one launch =================
// grid 128: cta -> dir(2) x ksec(4) x bg(2) x jt(8). block 256.
__global__ void __launch_bounds__(256)
enc_persist(const float* __restrict__ whpe,
            const float* __restrict__ bh_f, const float* __restrict__ bh_b,
            const int* __restrict__ src_lens,
            const float* __restrict__ gi_f, const float* __restrict__ gi_b,
            float* __restrict__ henc, float* __restrict__ wr_out,
            float* __restrict__ pgh) {
    int cta = blockIdx.x;
    int dir = cta & 1, ksec = (cta >> 1) & 3, bg = (cta >> 3) & 1, jt = cta >> 4;
    int tid = threadIdx.x;
    int tx = tid & 63, ty = tid >> 6;
    int j = jt * 64 + tx;
    int k0 = ksec * 128;
    const float* whp = whpe + (size_t)dir * (512 * 512 * 4);
    const float* bh = dir ? bh_b : bh_f;
    const float* gi = dir ? gi_b : gi_f;

    __shared__ float hs[16][128];
    unsigned epoch = 0;

    float br = 0.f, bz = 0.f, bn = 0.f;
    int lens[4] = {0, 0, 0, 0};
    if (ksec == 0) {
        br = bh[j]; bz = bh[512 + j]; bn = bh[1024 + j];
#pragma unroll
        for (int i = 0; i < 4; i++) lens[i] = max(src_lens[bg * 16 + i * 4 + ty], 1);
    }

    for (int step = 0; step < SS; step++) {
        int t = dir ? (SS - 1 - step) : step;
        int p = step & 1;
        const float* hin = henc + p * (BB * 1024);
        float* hout = henc + (p ^ 1) * (BB * 1024);

        // ---- phase 1: partial gh over k-range [k0, k0+128) ----
#pragma unroll
        for (int u = 0; u < 2; u++) {
            int idx = u * 256 + tid;          // 512 -> 16 b x 32 k4
            int bl = idx >> 5, k4 = idx & 31;
            int b = bg * 16 + bl;
            float4 h4 = ldcg4(&hin[b * 1024 + dir * 512 + k0 + k4 * 4]);
            *(float4*)&hs[bl][k4 * 4] = h4;
        }
        __syncthreads();

        float ar[4] = {0, 0, 0, 0}, az[4] = {0, 0, 0, 0}, an[4] = {0, 0, 0, 0};
#pragma unroll 4
        for (int kk = 0; kk < 128; kk++) {
            float4 w = *(const float4*)&whp[((size_t)(k0 + kk) << 11) + (j << 2)];
#pragma unroll
            for (int i = 0; i < 4; i++) {
                float hv = hs[i * 4 + ty][kk];
                ar[i] = fmaf(hv, w.x, ar[i]);
                az[i] = fmaf(hv, w.y, az[i]);
                an[i] = fmaf(hv, w.z, an[i]);
            }
        }

        if (ksec != 0) {
#pragma unroll
            for (int i = 0; i < 4; i++) {
                int b = bg * 16 + i * 4 + ty;
                int base = (((dir * 4 + ksec) * 3) * 32 + b) * 512 + j;
                pgh[base] = ar[i];
                pgh[base + 32 * 512] = az[i];
                pgh[base + 64 * 512] = an[i];
            }
        }
        gsync(&g_bar_enc, epoch, gridDim.x);

        // ---- phase 2: reduce + gates (ksec==0 CTAs only) ----
        if (ksec == 0) {
#pragma unroll
            for (int i = 0; i < 4; i++) {
                int b = bg * 16 + i * 4 + ty;
                float sr = ar[i], sz = az[i], sn = an[i];
#pragma unroll
                for (int s = 1; s < 4; s++) {
                    int base = (((dir * 4 + s) * 3) * 32 + b) * 512 + j;
                    sr += ldcg1(&pgh[base]);
                    sz += ldcg1(&pgh[base + 32 * 512]);
                    sn += ldcg1(&pgh[base + 64 * 512]);
                }
                size_t row = (size_t)(b * SS + t);
                float gir = gi[row * G3 + j];
                float giz = gi[row * G3 + 512 + j];
                float gin = gi[row * G3 + 1024 + j];
                float hold = ldcg1(&hin[b * 1024 + dir * 512 + j]);
                float r = sigm(gir + sr + br);
                float z = sigm(giz + sz + bz);
                float n = tanhf(gin + r * (sn + bn));
                float hnew = (1.0f - z) * n + z * hold;
                bool valid = t < lens[i];
                hout[b * 1024 + dir * 512 + j] = valid ? hnew : hold;
                wr_out[row * 1024 + dir * 512 + j] = valid ? hnew : 0.0f;
            }
        }
        gsync(&g_bar_enc, epoch, gridDim.x);
    }
}

// ================= persistent decoder: GRU + attention for all 63 steps =================
// grid 64: cta -> ksec(4) x bg(2) x jt(8). attention phase uses cta<32 (one per batch).
__global__ void __launch_bounds__(256)
dec_persist(const float* __restrict__ whpd, const float* __restrict__ bh,
            const float* __restrict__ gi,
            const float* __restrict__ Wq, const float* __restrict__ bq,
            const float* __restrict__ Kmat, const float* __restrict__ Vmat,
            float* __restrict__ hdec, float* __restrict__ hgru,
            float* __restrict__ hid_all, float* __restrict__ pgh) {
    int cta = blockIdx.x;
    int ksec = cta & 3, bg = (cta >> 2) & 1, jt = cta >> 3;
    int tid = threadIdx.x;
    int tx = tid & 63, ty = tid >> 6;
    int j = jt * 64 + tx;
    int k0 = ksec * 128;

    __shared__ float hs[16][128];
    __shared__ float hsh[DD];
    __shared__ float qsh[KKQ];
    __shared__ float ssh[SS];
    __shared__ float red[256];
    unsigned epoch = 0;

    float br = 0.f, bz = 0.f, bn = 0.f;
    if (ksec == 0) { br = bh[j]; bz = bh[512 + j]; bn = bh[1024 + j]; }

    for (int t = 0; t < TT - 1; t++) {
        // ---- phase A: partial gh = hdec @ Wh over k-range ----
#pragma unroll
        for (int u = 0; u < 2; u++) {
            int idx = u * 256 + tid;
            int bl = idx >> 5, k4 = idx & 31;
            int b = bg * 16 + bl;
            float4 h4 = ldcg4(&hdec[b * 512 + k0 + k4 * 4]);
            *(float4*)&hs[bl][k4 * 4] = h4;
        }
        __syncthreads();

        float ar[4] = {0, 0, 0, 0}, az[4] = {0, 0, 0, 0}, an[4] = {0, 0, 0, 0};
#pragma unroll 4
        for (int kk = 0; kk < 128; kk++) {
            float4 w = *(const float4*)&whpd[((size_t)(k0 + kk) << 11) + (j << 2)];
#pragma unroll
            for (int i = 0; i < 4; i++) {
                float hv = hs[i * 4 + ty][kk];
                ar[i] = fmaf(hv, w.x, ar[i]);
                az[i] = fmaf(hv, w.y, az[i]);
                an[i] = fmaf(hv, w.z, an[i]);
            }
        }
        if (ksec != 0) {
#pragma unroll
            for (int i = 0; i < 4; i++) {
                int b = bg * 16 + i * 4 + ty;
                int base = ((ksec * 3) * 32 + b) * 512 + j;
                pgh[base] = ar[i];
                pgh[base + 32 * 512] = az[i];
                pgh[base + 64 * 512] = an[i];
            }
        }
        gsync(&g_bar_dec, epoch, gridDim.x);

        // ---- phase B: reduce + GRU gates -> hgru ----
        if (ksec == 0) {
#pragma unroll
            for (int i = 0; i < 4; i++) {
                int b = bg * 16 + i * 4 + ty;
                float sr = ar[i], sz = az[i], sn = an[i];
#pragma unroll
                for (int s = 1; s < 4; s++) {
                    int base = ((s * 3) * 32 + b) * 512 + j;
                    sr += ldcg1(&pgh[base]);
                    sz += ldcg1(&pgh[base + 32 * 512]);
                    sn += ldcg1(&pgh[base + 64 * 512]);
                }
                size_t row = (size_t)(t * BB + b);
                float gir = gi[row * G3 + j];
                float giz = gi[row * G3 + 512 + j];
                float gin = gi[row * G3 + 1024 + j];
                float hold = ldcg1(&hdec[b * 512 + j]);
                float r = sigm(gir + sr + br);
                float z = sigm(giz + sz + bz);
                float n = tanhf(gin + r * (sn + bn));
                hgru[b * 512 + j] = (1.0f - z) * n + z * hold;
            }
        }
        gsync(&g_bar_dec, epoch, gridDim.x);

        // ---- phase C: attention (cta < 32, one per batch element) ----
        if (cta < BB) {
            int b = cta;
            for (int i = tid; i < DD; i += 256) hsh[i] = ldcg1(&hgru[b * 512 + i]);
            __syncthreads();
            {
                int jq = tid & 63, part = tid >> 6;
                float acc = 0.f;
                int kb = part * 128;
                for (int k = kb; k < kb + 128; k++) acc = fmaf(hsh[k], Wq[k * KKQ + jq], acc);
                red[tid] = acc;
            }
            __syncthreads();
            if (tid < KKQ) {
                float q = red[tid] + red[tid + 64] + red[tid + 128] + red[tid + 192] + bq[tid];
                qsh[tid] = q * 0.125f;
            }
            __syncthreads();
            if (tid < SS) {
                const float* Kp = Kmat + (size_t)(b * SS + tid) * KKQ;
                float sc = 0.f;
                for (int k = 0; k < KKQ; k++) sc = fmaf(qsh[k], Kp[k], sc);
                ssh[tid] = sc;
            }
            __syncthreads();
            if (tid == 0) {
                float m = ssh[0];
                for (int s = 1; s < SS; s++) m = fmaxf(m, ssh[s]);
                float sum = 0.f;
                for (int s = 0; s < SS; s++) { float e = expf(ssh[s] - m); ssh[s] = e; sum += e; }
                red[0] = 1.0f / sum;
            }
            __syncthreads();
            float inv = red[0];
            __syncthreads();
            if (tid < SS) ssh[tid] *= inv;
            __syncthreads();
            for (int d0 = tid; d0 < DD; d0 += 256) {
                float a = 0.f;
                for (int s = 0; s < SS; s++)
                    a = fmaf(ssh[s], Vmat[(size_t)(b * SS + s) * DD + d0], a);
                float hid = hsh[d0] + a;
                hdec[b * 512 + d0] = hid;
                hid_all[(size_t)(t * BB + b) * 512 + d0] = hid;
            }
        }
        gsync(&g_bar_dec, epoch, gridDim.x);
    }
}

// ---------------- fp32 -> fp16 conversions ----------------
__global__ void convert_x(const float* __restrict__ X, __half* __restrict__ Xh) {
    int i = blockIdx.x * blockDim.x + threadIdx.x;
    if (i >= MROWS * DD / 4) return;
    float4 v = ((const float4*)X)[i];
    __half2 a = __floats2half2_rn(v.x, v.y);
    __half2 b = __floats2half2_rn(v.z, v.w);
    uint2 pk;
    pk.x = *(uint32_t*)&a;
    pk.y = *(uint32_t*)&b;
    ((uint2*)Xh)[i] = pk;
}

// transpose W2 [K=512, N=32000] fp32 -> W2h [N, K] fp16
__global__ void transpose_w2(const float* __restrict__ W2, __half* __restrict__ W2h) {
    __shared__ float ts[32][33];
    int n0 = blockIdx.x * 32;
    int k0 = blockIdx.y * 32;
    int tx = threadIdx.x, ty = threadIdx.y;
#pragma unroll
    for (int j = 0; j < 4; j++)
        ts[ty + j * 8][tx] = W2[(size_t)(k0 + ty + j * 8) * VOC + n0 + tx];
    __syncthreads();
#pragma unroll
    for (int j = 0; j < 4; j++) {
        int n = n0 + ty + j * 8;
        int k = k0 + tx;
        W2h[(size_t)n * DD + k] = __float2half(ts[tx][ty + j * 8]);
    }
}

// ================= HMMA fp16 head GEMM: out = Xh @ W2h^T + b2 (remapped) =================
#define HPITCH 72

__device__ __forceinline__ uint32_t smem_u32(const void* p) {
    uint32_t a;
    asm("{ .reg .u64 t; cvta.to.shared.u64 t, %1; cvt.u32.u64 %0, t; }" : "=r"(a) : "l"(p));
    return a;
}
__device__ __forceinline__ void ldmatrix_x4(uint32_t* r, uint32_t addr) {
    asm volatile("ldmatrix.sync.aligned.m8n8.x4.shared.b16 {%0,%1,%2,%3}, [%4];"
                 : "=r"(r[0]), "=r"(r[1]), "=r"(r[2]), "=r"(r[3]) : "r"(addr));
}
__device__ __forceinline__ void ldmatrix_x2(uint32_t* r, uint32_t addr) {
    asm volatile("ldmatrix.sync.aligned.m8n8.x2.shared.b16 {%0,%1}, [%2];"
                 : "=r"(r[0]), "=r"(r[1]) : "r"(addr));
}
__device__ __forceinline__ void mma16816(float* c, const uint32_t* a, const uint32_t* b) {
    asm volatile(
        "mma.sync.aligned.m16n8k16.row.col.f32.f16.f16.f32 "
        "{%0,%1,%2,%3}, {%4,%5,%6,%7}, {%8,%9}, {%0,%1,%2,%3};"
        : "+f"(c[0]), "+f"(c[1]), "+f"(c[2]), "+f"(c[3])
        : "r"(a[0]), "r"(a[1]), "r"(a[2]), "r"(a[3]), "r"(b[0]), "r"(b[1]));
}

__global__ void __launch_bounds__(256, 2)
head_mma(const __half* __restrict__ Xh, const __half* __restrict__ W2h,
         const float* __restrict__ b2, float* __restrict__ out) {
    __shared__ __half As[128 * HPITCH];
    __shared__ __half Bs[128 * HPITCH];

    int tid = threadIdx.x;
    int wid = tid >> 5, lane = tid & 31;
    int m0 = blockIdx.x * 128;
    int n0 = blockIdx.y * 128;
    int wm = (wid >> 2) * 64;
    int wn = (wid & 3) * 32;

    float c[4][4][4];
#pragma unroll
    for (int mi = 0; mi < 4; mi++)
#pragma unroll
        for (int ni = 0; ni < 4; ni++)
#pragma unroll
            for (int q = 0; q < 4; q++) c[mi][ni][q] = 0.0f;

    uint32_t as_base = smem_u32(As);
    uint32_t bs_base = smem_u32(Bs);

    for (int kc = 0; kc < 8; kc++) {
        int k0 = kc * 64;
        __syncthreads();
#pragma unroll
        for (int it = 0; it < 4; it++) {
            int idx = it * 256 + tid;
            int row = idx >> 3;
            int col = (idx & 7) * 8;
            uint4 va = (m0 + row < MROWS)
                ? *(const uint4*)(Xh + (size_t)(m0 + row) * DD + k0 + col)
                : make_uint4(0, 0, 0, 0);
            *(uint4*)(As + row * HPITCH + col) = va;
            uint4 vb = *(const uint4*)(W2h + (size_t)(n0 + row) * DD + k0 + col);
            *(uint4*)(Bs + row * HPITCH + col) = vb;
        }
        __syncthreads();

#pragma unroll
        for (int k16 = 0; k16 < 4; k16++) {
            uint32_t afrag[4][4], bfrag[4][2];
#pragma unroll
            for (int mi = 0; mi < 4; mi++) {
                int r = wm + mi * 16 + (lane & 15);
                int cl = k16 * 16 + ((lane >> 4) * 8);
                ldmatrix_x4(afrag[mi], as_base + (uint32_t)(r * HPITCH + cl) * 2);
            }
#pragma unroll
            for (int ni = 0; ni < 4; ni++) {
                int r = wn + ni * 8 + (lane & 7);
                int cl = k16 * 16 + (((lane >> 3) & 1) * 8);
                ldmatrix_x2(bfrag[ni], bs_base + (uint32_t)(r * HPITCH + cl) * 2);
            }
#pragma unroll
            for (int mi = 0; mi < 4; mi++)
#pragma unroll
                for (int ni = 0; ni < 4; ni++)
                    mma16816(c[mi][ni], afrag[mi], bfrag[ni]);
        }
    }

    int rbase = lane >> 2;
    int cbase = (lane & 3) * 2;
#pragma unroll
    for (int mi = 0; mi < 4; mi++) {
#pragma unroll
        for (int half2i = 0; half2i < 2; half2i++) {
            int m = m0 + wm + mi * 16 + rbase + half2i * 8;
            if (m >= MROWS) continue;
            int b = m & 31, t = m >> 5;
            float* orow = out + (size_t)(b * TT + t + 1) * VOC;
#pragma unroll
            for (int ni = 0; ni < 4; ni++) {
                int n = n0 + wn + ni * 8 + cbase;
                float2 v;
                v.x = c[mi][ni][half2i * 2 + 0] + b2[n];
                v.y = c[mi][ni][half2i * 2 + 1] + b2[n + 1];
                *(float2*)(orow + n) = v;
            }
        }
    }
}

// ================================ host ================================
extern "C" void kernel_launch(void* const* d_in, const int* in_sizes, int n_in,
                              void* d_out, int out_size) {
    const int*   src       = (const int*)  d_in[0];
    const int*   trg       = (const int*)  d_in[1];
    const int*   src_lens  = (const int*)  d_in[2];
    const float* enc_embed = (const float*)d_in[3];
    const float* Wi_f      = (const float*)d_in[4];
    const float* Wh_f      = (const float*)d_in[5];
    const float* bi_f      = (const float*)d_in[6];
    const float* bh_f      = (const float*)d_in[7];
    const float* Wi_b      = (const float*)d_in[8];
    const float* Wh_b      = (const float*)d_in[9];
    const float* bi_b      = (const float*)d_in[10];
    const float* bh_b      = (const float*)d_in[11];
    const float* W_e2d     = (const float*)d_in[12];
    const float* b_e2d     = (const float*)d_in[13];
    const float* dec_embed = (const float*)d_in[14];
    const float* Wi_d      = (const float*)d_in[15];
    const float* Wh_d      = (const float*)d_in[16];
    const float* bi_d      = (const float*)d_in[17];
    const float* bh_d      = (const float*)d_in[18];
    const float* Wq        = (const float*)d_in[19];
    const float* bq        = (const float*)d_in[20];
    const float* Wk        = (const float*)d_in[21];
    const float* bk        = (const float*)d_in[22];
    const float* Wv        = (const float*)d_in[23];
    const float* bv        = (const float*)d_in[24];
    const float* W1        = (const float*)d_in[25];
    const float* b1        = (const float*)d_in[26];
    const float* W2        = (const float*)d_in[27];
    const float* b2        = (const float*)d_in[28];
    float* out = (float*)d_out;

    float* scr = nullptr;
    cudaGetSymbolAddress((void**)&scr, g_scr);
    __half* xh = nullptr;
    cudaGetSymbolAddress((void**)&xh, g_xh);
    __half* w2h = nullptr;
    cudaGetSymbolAddress((void**)&w2h, g_w2h);

    float* p_emb  = scr;
    float* p_gif  = p_emb  + NF_EMB;
    float* p_gib  = p_gif  + NF_GI;
    float* p_wr   = p_gib  + NF_GI;
    float* p_henc = p_wr   + NF_WR;
    float* p_K    = p_henc + NF_HENC;
    float* p_V    = p_K    + NF_K;
    float* p_demb = p_V    + NF_V;
    float* p_gid  = p_demb + NF_DEMB;
    float* p_hdec = p_gid  + NF_GID;
    float* p_hgru = p_hdec + NF_HDEC;
    float* p_hid  = p_hgru + NF_HGRU;
    float* p_X    = p_hid  + NF_HID;
    float* p_whpe = p_X    + NF_X;
    float* p_whpd = p_whpe + NF_WHPE;
    float* p_pgh  = p_whpd + NF_WHPD;

    // 0) zero init + barrier reset
    init_zero<<<(BB * VOC + 255) / 256, 256>>>(out, p_henc);

    // weight prep (independent)
    transpose_w2<<<dim3(VOC / 32, DD / 32), dim3(32, 8)>>>(W2, w2h);
    pack_wh<<<(512 * 512 + 255) / 256, 256>>>(Wh_f, Wh_b, Wh_d, p_whpe, p_whpd);

    // 1) encoder input embeddings + input projections
    gather_src<<<(BB * SS * (EE / 4) + 255) / 256, 256>>>(src, enc_embed, p_emb);
    gemm_k<0><<<dim3(G3 / 64, (BB * SS) / 64), 256>>>(p_emb, Wi_f, bi_f, p_gif, BB * SS, G3, EE);
    gemm_k<0><<<dim3(G3 / 64, (BB * SS) / 64), 256>>>(p_emb, Wi_b, bi_b, p_gib, BB * SS, G3, EE);

    // 2) encoder recurrence: single persistent kernel
    enc_persist<<<128, 256>>>(p_whpe, bh_f, bh_b, src_lens, p_gif, p_gib,
                              p_henc, p_wr, p_pgh);
    float* p_sent = p_henc;   // 64 steps -> parity 0

    // 3) K, V projections and decoder initial state
    gemm_k<0><<<dim3(KKQ / 64, (BB * SS) / 64), 256>>>(p_wr, Wk, bk, p_K, BB * SS, KKQ, 2 * HH);
    gemm_k<0><<<dim3(DD / 64, (BB * SS) / 64), 256>>>(p_wr, Wv, bv, p_V, BB * SS, DD, 2 * HH);
    gemm_k<1><<<dim3(DD / 64, 1), 256>>>(p_sent, W_e2d, b_e2d, p_hdec, BB, DD, 2 * HH);

    // 4) decoder input embeddings + input projections
    gather_trg<<<(BB * (TT - 1) * (EE / 4) + 255) / 256, 256>>>(trg, dec_embed, p_demb);
    gemm_k<0><<<dim3(G3 / 64, (BB * (TT - 1) + 63) / 64), 256>>>(p_demb, Wi_d, bi_d, p_gid,
                                                                 BB * (TT - 1), G3, EE);

    // 5) decoder recurrence: single persistent kernel (GRU + attention)
    dec_persist<<<64, 256>>>(p_whpd, bh_d, p_gid, Wq, bq, p_K, p_V,
                             p_hdec, p_hgru, p_hid, p_pgh);

    // 6) output head
    gemm_k<1><<<dim3(DD / 64, (BB * (TT - 1) + 63) / 64), 256>>>(p_hid, W1, b1, p_X,
                                                                 BB * (TT - 1), DD, DD);
    convert_x<<<(MROWS * DD / 4 + 255) / 256, 256>>>(p_X, xh);
    head_mma<<<dim3((MROWS + 127) / 128, VOC / 128), 256>>>(xh, w2h, b2, out);
}

// round 6
// speedup vs baseline: 4.9096x; 1.4620x over previous
#include <cuda_runtime.h>
#include <cuda_fp16.h>
#include <cstdint>
#include <math.h>

#define BB   32
#define SS   64
#define TT   64
#define EE   256
#define HH   512
#define DD   512
#define KKQ  64
#define VOC  32000
#define G3   1536
#define MROWS (BB*(TT-1))   // 2016

#define NF_EMB   (BB*SS*EE)
#define NF_GI    (BB*SS*G3)
#define NF_WR    (BB*SS*2*HH)
#define NF_HENC  (2*BB*2*HH)
#define NF_K     (BB*SS*KKQ)
#define NF_V     (BB*SS*DD)
#define NF_DEMB  (BB*(TT-1)*EE)
#define NF_GID   (BB*(TT-1)*G3)
#define NF_HDEC  (BB*DD)
#define NF_HID   (BB*(TT-1)*DD)
#define NF_WHPE  (2*512*512*4)
#define NF_WHPD  (512*512*4)
#define NF_PGH   (2*4*3*32*512)

#define NF_TOTAL (NF_EMB + 2*NF_GI + NF_WR + NF_HENC + NF_K + NF_V + NF_DEMB + NF_GID + \
                  NF_HDEC + NF_HID + NF_WHPE + NF_WHPD + NF_PGH)

__device__ float g_scr[NF_TOTAL];
__device__ __half g_xh[MROWS * DD];
__device__ __half g_w2h[VOC * DD];
__device__ unsigned g_bar_enc;
__device__ unsigned g_bar_dec;

__device__ __forceinline__ float sigm(float x) { return 1.0f / (1.0f + expf(-x)); }
__device__ __forceinline__ float gelu_f(float x) { return 0.5f * x * (1.0f + erff(x * 0.7071067811865475f)); }

__device__ __forceinline__ float ldcg1(const float* p) {
    float v; asm volatile("ld.global.cg.f32 %0, [%1];" : "=f"(v) : "l"(p)); return v;
}
__device__ __forceinline__ float4 ldcg4(const float* p) {
    float4 v;
    asm volatile("ld.global.cg.v4.f32 {%0,%1,%2,%3}, [%4];"
                 : "=f"(v.x), "=f"(v.y), "=f"(v.z), "=f"(v.w) : "l"(p));
    return v;
}

// software grid barrier: all CTAs resident
__device__ __forceinline__ void gsync(unsigned* bar, unsigned& epoch, unsigned nb) {
    __syncthreads();
    if (threadIdx.x == 0) {
        epoch += nb;
        __threadfence();
        atomicAdd(bar, 1u);
        while (*(volatile unsigned*)bar < epoch) __nanosleep(32);
        __threadfence();
    }
    __syncthreads();
}

// ---------------- init ----------------
__global__ void init_zero(float* __restrict__ out, float* __restrict__ henc) {
    int i = blockIdx.x * blockDim.x + threadIdx.x;
    if (i == 0) { g_bar_enc = 0; g_bar_dec = 0; }
    if (i < BB * VOC) {
        int b = i / VOC;
        out[(size_t)b * TT * VOC + (i % VOC)] = 0.0f;
    }
    if (i < NF_HENC) henc[i] = 0.0f;
}

// ---------------- embedding gathers ----------------
__global__ void gather_src(const int* __restrict__ src, const float* __restrict__ tab,
                           float* __restrict__ emb) {
    int i = blockIdx.x * blockDim.x + threadIdx.x;
    if (i >= BB * SS * (EE / 4)) return;
    int row = i / (EE / 4);
    int c   = i % (EE / 4);
    ((float4*)emb)[row * (EE / 4) + c] =
        ((const float4*)tab)[(size_t)src[row] * (EE / 4) + c];
}

__global__ void gather_trg(const int* __restrict__ trg, const float* __restrict__ tab,
                           float* __restrict__ demb) {
    int i = blockIdx.x * blockDim.x + threadIdx.x;
    if (i >= BB * (TT - 1) * (EE / 4)) return;
    int m = i / (EE / 4);
    int c = i % (EE / 4);
    int t = m / BB, b = m % BB;
    int tok = trg[b * TT + t];
    ((float4*)demb)[m * (EE / 4) + c] =
        ((const float4*)tab)[(size_t)tok * (EE / 4) + c];
}

// ---------------- pack recurrent weights ----------------
__global__ void pack_wh(const float* __restrict__ Wh_f, const float* __restrict__ Wh_b,
                        const float* __restrict__ Wh_d,
                        float* __restrict__ whpe, float* __restrict__ whpd) {
    int idx = blockIdx.x * blockDim.x + threadIdx.x;
    if (idx >= 512 * 512) return;
    int k = idx >> 9, j = idx & 511;
    float4 vf = make_float4(Wh_f[k * G3 + j], Wh_f[k * G3 + 512 + j], Wh_f[k * G3 + 1024 + j], 0.f);
    float4 vb = make_float4(Wh_b[k * G3 + j], Wh_b[k * G3 + 512 + j], Wh_b[k * G3 + 1024 + j], 0.f);
    float4 vd = make_float4(Wh_d[k * G3 + j], Wh_d[k * G3 + 512 + j], Wh_d[k * G3 + 1024 + j], 0.f);
    ((float4*)whpe)[idx] = vf;
    ((float4*)whpe)[512 * 512 + idx] = vb;
    ((float4*)whpd)[idx] = vd;
}

// ---------------- generic fp32 GEMM ----------------
template<int GELU, int OUT16>
__global__ void gemm_k(const float* __restrict__ A, const float* __restrict__ Bm,
                       const float* __restrict__ bias, void* __restrict__ Cv,
                       int M, int N, int K) {
    __shared__ float As[16][68];
    __shared__ float Bs[16][68];
    int tid = threadIdx.x;
    int m0 = blockIdx.y * 64, n0 = blockIdx.x * 64;
    int tx = tid & 15, ty = tid >> 4;

    float acc[4][4];
#pragma unroll
    for (int i = 0; i < 4; i++)
#pragma unroll
        for (int j = 0; j < 4; j++) acc[i][j] = 0.0f;

    int lam = tid >> 2;
    int lak = (tid & 3) * 4;
    int lbk = tid >> 4;
    int lbn = (tid & 15) * 4;

    for (int k0 = 0; k0 < K; k0 += 16) {
        float4 av = (m0 + lam < M)
            ? *(const float4*)&A[(size_t)(m0 + lam) * K + k0 + lak]
            : make_float4(0.f, 0.f, 0.f, 0.f);
        float4 bv = *(const float4*)&Bm[(size_t)(k0 + lbk) * N + n0 + lbn];
        __syncthreads();
        As[lak + 0][lam] = av.x;
        As[lak + 1][lam] = av.y;
        As[lak + 2][lam] = av.z;
        As[lak + 3][lam] = av.w;
        *(float4*)&Bs[lbk][lbn] = bv;
        __syncthreads();
#pragma unroll
        for (int kk = 0; kk < 16; kk++) {
            float4 a4 = *(const float4*)&As[kk][ty * 4];
            float4 b4 = *(const float4*)&Bs[kk][tx * 4];
            float a[4] = {a4.x, a4.y, a4.z, a4.w};
            float b[4] = {b4.x, b4.y, b4.z, b4.w};
#pragma unroll
            for (int i = 0; i < 4; i++)
#pragma unroll
                for (int j = 0; j < 4; j++) acc[i][j] = fmaf(a[i], b[j], acc[i][j]);
        }
    }

#pragma unroll
    for (int i = 0; i < 4; i++) {
        int m = m0 + ty * 4 + i;
        if (m >= M) continue;
#pragma unroll
        for (int j = 0; j < 4; j++) {
            int n = n0 + tx * 4 + j;
            float v = acc[i][j] + bias[n];
            if (GELU) v = gelu_f(v);
            if (OUT16) ((__half*)Cv)[(size_t)m * N + n] = __float2half(v);
            else       ((float*)Cv)[(size_t)m * N + n] = v;
        }
    }
}

// ================= persistent encoder =================
// grid 128: dir(2) x ksec(4) x bg(2) x jt(8); weights cached in SMEM.
// dyn smem: ws4 128k x 64j float4 (131072 B) + hs 16b x 128k floats (8192 B)
#define ENC_SMEM (131072 + 8192)
__global__ void __launch_bounds__(256, 1)
enc_persist(const float* __restrict__ whpe,
            const float* __restrict__ bh_f, const float* __restrict__ bh_b,
            const int* __restrict__ src_lens,
            const float* __restrict__ gi_f, const float* __restrict__ gi_b,
            float* __restrict__ henc, float* __restrict__ wr_out,
            float* __restrict__ pgh) {
    extern __shared__ float smem[];
    float4* ws4 = (float4*)smem;          // [128][64]
    float*  hsf = smem + 32768;           // [16][128]

    int cta = blockIdx.x;
    int dir = cta & 1, ksec = (cta >> 1) & 3, bg = (cta >> 3) & 1, jt = cta >> 4;
    int tid = threadIdx.x;
    int tx = tid & 63, ty = tid >> 6;
    int j = jt * 64 + tx;
    int k0 = ksec * 128;
    const float* whp = whpe + (size_t)dir * (512 * 512 * 4);
    const float* bh = dir ? bh_b : bh_f;
    const float* gi = dir ? gi_b : gi_f;

    // cache weight slab: 8192 float4, 32 per thread, coalesced
#pragma unroll
    for (int u = 0; u < 32; u++) {
        int idx = u * 256 + tid;
        int kk = idx >> 6, jl = idx & 63;
        ws4[idx] = *(const float4*)&whp[((size_t)(k0 + kk) << 11) + ((jt * 64 + jl) << 2)];
    }

    unsigned epoch = 0;
    float br = 0.f, bz = 0.f, bn = 0.f;
    int lens[4] = {0, 0, 0, 0};
    if (ksec == 0) {
        br = bh[j]; bz = bh[512 + j]; bn = bh[1024 + j];
#pragma unroll
        for (int i = 0; i < 4; i++) lens[i] = max(src_lens[bg * 16 + i * 4 + ty], 1);
    }
    __syncthreads();

    for (int step = 0; step < SS; step++) {
        int t = dir ? (SS - 1 - step) : step;
        int p = step & 1;
        const float* hin = henc + p * (BB * 1024);
        float* hout = henc + (p ^ 1) * (BB * 1024);

        // phase 1: partial gh over [k0, k0+128)
#pragma unroll
        for (int u = 0; u < 2; u++) {
            int idx = u * 256 + tid;
            int bl = idx >> 5, k4 = idx & 31;
            int b = bg * 16 + bl;
            float4 h4 = ldcg4(&hin[b * 1024 + dir * 512 + k0 + k4 * 4]);
            *(float4*)&hsf[bl * 128 + k4 * 4] = h4;
        }
        __syncthreads();

        float ar[4] = {0, 0, 0, 0}, az[4] = {0, 0, 0, 0}, an[4] = {0, 0, 0, 0};
#pragma unroll 8
        for (int kk = 0; kk < 128; kk++) {
            float4 w = ws4[kk * 64 + tx];
#pragma unroll
            for (int i = 0; i < 4; i++) {
                float hv = hsf[(i * 4 + ty) * 128 + kk];
                ar[i] = fmaf(hv, w.x, ar[i]);
                az[i] = fmaf(hv, w.y, az[i]);
                an[i] = fmaf(hv, w.z, an[i]);
            }
        }

        if (ksec != 0) {
#pragma unroll
            for (int i = 0; i < 4; i++) {
                int b = bg * 16 + i * 4 + ty;
                int base = (((dir * 4 + ksec) * 3) * 32 + b) * 512 + j;
                pgh[base] = ar[i];
                pgh[base + 32 * 512] = az[i];
                pgh[base + 64 * 512] = an[i];
            }
        }
        gsync(&g_bar_enc, epoch, gridDim.x);

        // phase 2: reduce + gates (ksec==0)
        if (ksec == 0) {
#pragma unroll
            for (int i = 0; i < 4; i++) {
                int b = bg * 16 + i * 4 + ty;
                float sr = ar[i], sz = az[i], sn = an[i];
#pragma unroll
                for (int s = 1; s < 4; s++) {
                    int base = (((dir * 4 + s) * 3) * 32 + b) * 512 + j;
                    sr += ldcg1(&pgh[base]);
                    sz += ldcg1(&pgh[base + 32 * 512]);
                    sn += ldcg1(&pgh[base + 64 * 512]);
                }
                size_t row = (size_t)(b * SS + t);
                float gir = gi[row * G3 + j];
                float giz = gi[row * G3 + 512 + j];
                float gin = gi[row * G3 + 1024 + j];
                float hold = ldcg1(&hin[b * 1024 + dir * 512 + j]);
                float r = sigm(gir + sr + br);
                float z = sigm(giz + sz + bz);
                float n = tanhf(gin + r * (sn + bn));
                float hnew = (1.0f - z) * n + z * hold;
                bool valid = t < lens[i];
                hout[b * 1024 + dir * 512 + j] = valid ? hnew : hold;
                wr_out[row * 1024 + dir * 512 + j] = valid ? hnew : 0.0f;
            }
        }
        gsync(&g_bar_enc, epoch, gridDim.x);
    }
}

// ================= persistent decoder =================
// grid 128: ksec(8) x bg(2) x jt(8). 2 barriers/step: partials -> (reduce+gates+attn).
// dyn smem: ws4 64k x 64j float4 (65536 B) + hs 16b x 64k floats (4096 B)
#define DEC_SMEM (65536 + 4096)
__global__ void __launch_bounds__(256, 1)
dec_persist(const float* __restrict__ whpd, const float* __restrict__ bh,
            const float* __restrict__ gi,
            const float* __restrict__ Wq, const float* __restrict__ bq,
            const float* __restrict__ Kmat, const float* __restrict__ Vmat,
            float* __restrict__ hdec, float* __restrict__ hid_all,
            float* __restrict__ pgh) {
    extern __shared__ float smem[];
    float4* ws4 = (float4*)smem;          // [64][64]
    float*  hsf = smem + 16384;           // [16][64]
    __shared__ float hsh[DD];
    __shared__ float qsh[KKQ];
    __shared__ float ssh[SS];
    __shared__ float red[256];

    int cta = blockIdx.x;
    int ksec = cta & 7, bg = (cta >> 3) & 1, jt = cta >> 4;
    int tid = threadIdx.x;
    int tx = tid & 63, ty = tid >> 6;
    int j = jt * 64 + tx;
    int k0 = ksec * 64;

    // cache weight slab: 4096 float4, 16 per thread
#pragma unroll
    for (int u = 0; u < 16; u++) {
        int idx = u * 256 + tid;
        int kk = idx >> 6, jl = idx & 63;
        ws4[idx] = *(const float4*)&whpd[((size_t)(k0 + kk) << 11) + ((jt * 64 + jl) << 2)];
    }
    __syncthreads();

    unsigned epoch = 0;

    for (int t = 0; t < TT - 1; t++) {
        // phase A: partial gh over [k0, k0+64) for 16 batches
        {
            int bl = tid >> 4, k4 = tid & 15;
            int b = bg * 16 + bl;
            float4 h4 = ldcg4(&hdec[b * 512 + k0 + k4 * 4]);
            *(float4*)&hsf[bl * 64 + k4 * 4] = h4;
        }
        __syncthreads();

        float ar[4] = {0, 0, 0, 0}, az[4] = {0, 0, 0, 0}, an[4] = {0, 0, 0, 0};
#pragma unroll 8
        for (int kk = 0; kk < 64; kk++) {
            float4 w = ws4[kk * 64 + tx];
#pragma unroll
            for (int i = 0; i < 4; i++) {
                float hv = hsf[(i * 4 + ty) * 64 + kk];
                ar[i] = fmaf(hv, w.x, ar[i]);
                az[i] = fmaf(hv, w.y, az[i]);
                an[i] = fmaf(hv, w.z, an[i]);
            }
        }
#pragma unroll
        for (int i = 0; i < 4; i++) {
            int b = bg * 16 + i * 4 + ty;
            int base = ((ksec * 3) * 32 + b) * 512 + j;
            pgh[base] = ar[i];
            pgh[base + 32 * 512] = az[i];
            pgh[base + 64 * 512] = an[i];
        }
        gsync(&g_bar_dec, epoch, gridDim.x);

        // phase B: fused reduce + gates + attention (cta < 32, one per batch)
        if (cta < BB) {
            int b = cta;
            size_t row = (size_t)(t * BB + b);
#pragma unroll
            for (int rr = 0; rr < 2; rr++) {
                int jj = rr * 256 + tid;
                float sr = 0.f, sz = 0.f, sn = 0.f;
#pragma unroll
                for (int s = 0; s < 8; s++) {
                    int base = ((s * 3) * 32 + b) * 512 + jj;
                    sr += ldcg1(&pgh[base]);
                    sz += ldcg1(&pgh[base + 32 * 512]);
                    sn += ldcg1(&pgh[base + 64 * 512]);
                }
                float gir = gi[row * G3 + jj];
                float giz = gi[row * G3 + 512 + jj];
                float gin = gi[row * G3 + 1024 + jj];
                float hold = ldcg1(&hdec[b * 512 + jj]);
                float r = sigm(gir + sr + bh[jj]);
                float z = sigm(giz + sz + bh[512 + jj]);
                float n = tanhf(gin + r * (sn + bh[1024 + jj]));
                hsh[jj] = (1.0f - z) * n + z * hold;
            }
            __syncthreads();

            // q = hgru @ Wq + bq (scaled)
            {
                int jq = tid & 63, part = tid >> 6;
                float acc = 0.f;
                int kb = part * 128;
                for (int k = kb; k < kb + 128; k++) acc = fmaf(hsh[k], Wq[k * KKQ + jq], acc);
                red[tid] = acc;
            }
            __syncthreads();
            if (tid < KKQ) {
                float q = red[tid] + red[tid + 64] + red[tid + 128] + red[tid + 192] + bq[tid];
                qsh[tid] = q * 0.125f;
            }
            __syncthreads();
            if (tid < SS) {
                const float* Kp = Kmat + (size_t)(b * SS + tid) * KKQ;
                float sc = 0.f;
                for (int k = 0; k < KKQ; k++) sc = fmaf(qsh[k], Kp[k], sc);
                ssh[tid] = sc;
            }
            __syncthreads();
            if (tid == 0) {
                float m = ssh[0];
                for (int s = 1; s < SS; s++) m = fmaxf(m, ssh[s]);
                float sum = 0.f;
                for (int s = 0; s < SS; s++) { float e = expf(ssh[s] - m); ssh[s] = e; sum += e; }
                red[0] = 1.0f / sum;
            }
            __syncthreads();
            float inv = red[0];
            __syncthreads();
            if (tid < SS) ssh[tid] *= inv;
            __syncthreads();
            for (int d0 = tid; d0 < DD; d0 += 256) {
                float a = 0.f;
                for (int s = 0; s < SS; s++)
                    a = fmaf(ssh[s], Vmat[(size_t)(b * SS + s) * DD + d0], a);
                float hid = hsh[d0] + a;
                hdec[b * 512 + d0] = hid;
                hid_all[row * 512 + d0] = hid;
            }
        }
        gsync(&g_bar_dec, epoch, gridDim.x);
    }
}

// transpose W2 [K=512, N=32000] fp32 -> W2h [N, K] fp16
__global__ void transpose_w2(const float* __restrict__ W2, __half* __restrict__ W2h) {
    __shared__ float ts[32][33];
    int n0 = blockIdx.x * 32;
    int k0 = blockIdx.y * 32;
    int tx = threadIdx.x, ty = threadIdx.y;
#pragma unroll
    for (int j = 0; j < 4; j++)
        ts[ty + j * 8][tx] = W2[(size_t)(k0 + ty + j * 8) * VOC + n0 + tx];
    __syncthreads();
#pragma unroll
    for (int j = 0; j < 4; j++) {
        int n = n0 + ty + j * 8;
        int k = k0 + tx;
        W2h[(size_t)n * DD + k] = __float2half(ts[tx][ty + j * 8]);
    }
}

// ================= HMMA fp16 head GEMM =================
#define HPITCH 72

__device__ __forceinline__ uint32_t smem_u32(const void* p) {
    uint32_t a;
    asm("{ .reg .u64 t; cvta.to.shared.u64 t, %1; cvt.u32.u64 %0, t; }" : "=r"(a) : "l"(p));
    return a;
}
__device__ __forceinline__ void ldmatrix_x4(uint32_t* r, uint32_t addr) {
    asm volatile("ldmatrix.sync.aligned.m8n8.x4.shared.b16 {%0,%1,%2,%3}, [%4];"
                 : "=r"(r[0]), "=r"(r[1]), "=r"(r[2]), "=r"(r[3]) : "r"(addr));
}
__device__ __forceinline__ void ldmatrix_x2(uint32_t* r, uint32_t addr) {
    asm volatile("ldmatrix.sync.aligned.m8n8.x2.shared.b16 {%0,%1}, [%2];"
                 : "=r"(r[0]), "=r"(r[1]) : "r"(addr));
}
__device__ __forceinline__ void mma16816(float* c, const uint32_t* a, const uint32_t* b) {
    asm volatile(
        "mma.sync.aligned.m16n8k16.row.col.f32.f16.f16.f32 "
        "{%0,%1,%2,%3}, {%4,%5,%6,%7}, {%8,%9}, {%0,%1,%2,%3};"
        : "+f"(c[0]), "+f"(c[1]), "+f"(c[2]), "+f"(c[3])
        : "r"(a[0]), "r"(a[1]), "r"(a[2]), "r"(a[3]), "r"(b[0]), "r"(b[1]));
}

__global__ void __launch_bounds__(256, 2)
head_mma(const __half* __restrict__ Xh, const __half* __restrict__ W2h,
         const float* __restrict__ b2, float* __restrict__ out) {
    __shared__ __half As[128 * HPITCH];
    __shared__ __half Bs[128 * HPITCH];

    int tid = threadIdx.x;
    int wid = tid >> 5, lane = tid & 31;
    int m0 = blockIdx.x * 128;
    int n0 = blockIdx.y * 128;
    int wm = (wid >> 2) * 64;
    int wn = (wid & 3) * 32;

    float c[4][4][4];
#pragma unroll
    for (int mi = 0; mi < 4; mi++)
#pragma unroll
        for (int ni = 0; ni < 4; ni++)
#pragma unroll
            for (int q = 0; q < 4; q++) c[mi][ni][q] = 0.0f;

    uint32_t as_base = smem_u32(As);
    uint32_t bs_base = smem_u32(Bs);

    for (int kc = 0; kc < 8; kc++) {
        int k0 = kc * 64;
        __syncthreads();
#pragma unroll
        for (int it = 0; it < 4; it++) {
            int idx = it * 256 + tid;
            int row = idx >> 3;
            int col = (idx & 7) * 8;
            uint4 va = (m0 + row < MROWS)
                ? *(const uint4*)(Xh + (size_t)(m0 + row) * DD + k0 + col)
                : make_uint4(0, 0, 0, 0);
            *(uint4*)(As + row * HPITCH + col) = va;
            uint4 vb = *(const uint4*)(W2h + (size_t)(n0 + row) * DD + k0 + col);
            *(uint4*)(Bs + row * HPITCH + col) = vb;
        }
        __syncthreads();

#pragma unroll
        for (int k16 = 0; k16 < 4; k16++) {
            uint32_t afrag[4][4], bfrag[4][2];
#pragma unroll
            for (int mi = 0; mi < 4; mi++) {
                int r = wm + mi * 16 + (lane & 15);
                int cl = k16 * 16 + ((lane >> 4) * 8);
                ldmatrix_x4(afrag[mi], as_base + (uint32_t)(r * HPITCH + cl) * 2);
            }
#pragma unroll
            for (int ni = 0; ni < 4; ni++) {
                int r = wn + ni * 8 + (lane & 7);
                int cl = k16 * 16 + (((lane >> 3) & 1) * 8);
                ldmatrix_x2(bfrag[ni], bs_base + (uint32_t)(r * HPITCH + cl) * 2);
            }
#pragma unroll
            for (int mi = 0; mi < 4; mi++)
#pragma unroll
                for (int ni = 0; ni < 4; ni++)
                    mma16816(c[mi][ni], afrag[mi], bfrag[ni]);
        }
    }

    int rbase = lane >> 2;
    int cbase = (lane & 3) * 2;
#pragma unroll
    for (int mi = 0; mi < 4; mi++) {
#pragma unroll
        for (int half2i = 0; half2i < 2; half2i++) {
            int m = m0 + wm + mi * 16 + rbase + half2i * 8;
            if (m >= MROWS) continue;
            int b = m & 31, t = m >> 5;
            float* orow = out + (size_t)(b * TT + t + 1) * VOC;
#pragma unroll
            for (int ni = 0; ni < 4; ni++) {
                int n = n0 + wn + ni * 8 + cbase;
                float2 v;
                v.x = c[mi][ni][half2i * 2 + 0] + b2[n];
                v.y = c[mi][ni][half2i * 2 + 1] + b2[n + 1];
                *(float2*)(orow + n) = v;
            }
        }
    }
}

// ================================ host ================================
extern "C" void kernel_launch(void* const* d_in, const int* in_sizes, int n_in,
                              void* d_out, int out_size) {
    const int*   src       = (const int*)  d_in[0];
    const int*   trg       = (const int*)  d_in[1];
    const int*   src_lens  = (const int*)  d_in[2];
    const float* enc_embed = (const float*)d_in[3];
    const float* Wi_f      = (const float*)d_in[4];
    const float* Wh_f      = (const float*)d_in[5];
    const float* bi_f      = (const float*)d_in[6];
    const float* bh_f      = (const float*)d_in[7];
    const float* Wi_b      = (const float*)d_in[8];
    const float* Wh_b      = (const float*)d_in[9];
    const float* bi_b      = (const float*)d_in[10];
    const float* bh_b      = (const float*)d_in[11];
    const float* W_e2d     = (const float*)d_in[12];
    const float* b_e2d     = (const float*)d_in[13];
    const float* dec_embed = (const float*)d_in[14];
    const float* Wi_d      = (const float*)d_in[15];
    const float* Wh_d      = (const float*)d_in[16];
    const float* bi_d      = (const float*)d_in[17];
    const float* bh_d      = (const float*)d_in[18];
    const float* Wq        = (const float*)d_in[19];
    const float* bq        = (const float*)d_in[20];
    const float* Wk        = (const float*)d_in[21];
    const float* bk        = (const float*)d_in[22];
    const float* Wv        = (const float*)d_in[23];
    const float* bv        = (const float*)d_in[24];
    const float* W1        = (const float*)d_in[25];
    const float* b1        = (const float*)d_in[26];
    const float* W2        = (const float*)d_in[27];
    const float* b2        = (const float*)d_in[28];
    float* out = (float*)d_out;

    float* scr = nullptr;
    cudaGetSymbolAddress((void**)&scr, g_scr);
    __half* xh = nullptr;
    cudaGetSymbolAddress((void**)&xh, g_xh);
    __half* w2h = nullptr;
    cudaGetSymbolAddress((void**)&w2h, g_w2h);

    float* p_emb  = scr;
    float* p_gif  = p_emb  + NF_EMB;
    float* p_gib  = p_gif  + NF_GI;
    float* p_wr   = p_gib  + NF_GI;
    float* p_henc = p_wr   + NF_WR;
    float* p_K    = p_henc + NF_HENC;
    float* p_V    = p_K    + NF_K;
    float* p_demb = p_V    + NF_V;
    float* p_gid  = p_demb + NF_DEMB;
    float* p_hdec = p_gid  + NF_GID;
    float* p_hid  = p_hdec + NF_HDEC;
    float* p_whpe = p_hid  + NF_HID;
    float* p_whpd = p_whpe + NF_WHPE;
    float* p_pgh  = p_whpd + NF_WHPD;

    static int attr_set = 0;
    if (!attr_set) {
        cudaFuncSetAttribute(enc_persist, cudaFuncAttributeMaxDynamicSharedMemorySize, ENC_SMEM);
        cudaFuncSetAttribute(dec_persist, cudaFuncAttributeMaxDynamicSharedMemorySize, DEC_SMEM);
        attr_set = 1;
    }

    // 0) zero init + barrier reset
    init_zero<<<(BB * VOC + 255) / 256, 256>>>(out, p_henc);

    // weight prep
    transpose_w2<<<dim3(VOC / 32, DD / 32), dim3(32, 8)>>>(W2, w2h);
    pack_wh<<<(512 * 512 + 255) / 256, 256>>>(Wh_f, Wh_b, Wh_d, p_whpe, p_whpd);

    // 1) encoder input embeddings + input projections
    gather_src<<<(BB * SS * (EE / 4) + 255) / 256, 256>>>(src, enc_embed, p_emb);
    gemm_k<0,0><<<dim3(G3 / 64, (BB * SS) / 64), 256>>>(p_emb, Wi_f, bi_f, p_gif, BB * SS, G3, EE);
    gemm_k<0,0><<<dim3(G3 / 64, (BB * SS) / 64), 256>>>(p_emb, Wi_b, bi_b, p_gib, BB * SS, G3, EE);

    // 2) encoder recurrence (persistent, smem-cached weights)
    enc_persist<<<128, 256, ENC_SMEM>>>(p_whpe, bh_f, bh_b, src_lens, p_gif, p_gib,
                                        p_henc, p_wr, p_pgh);
    float* p_sent = p_henc;

    // 3) K, V projections and decoder initial state
    gemm_k<0,0><<<dim3(KKQ / 64, (BB * SS) / 64), 256>>>(p_wr, Wk, bk, p_K, BB * SS, KKQ, 2 * HH);
    gemm_k<0,0><<<dim3(DD / 64, (BB * SS) / 64), 256>>>(p_wr, Wv, bv, p_V, BB * SS, DD, 2 * HH);
    gemm_k<1,0><<<dim3(DD / 64, 1), 256>>>(p_sent, W_e2d, b_e2d, p_hdec, BB, DD, 2 * HH);

    // 4) decoder input embeddings + input projections
    gather_trg<<<(BB * (TT - 1) * (EE / 4) + 255) / 256, 256>>>(trg, dec_embed, p_demb);
    gemm_k<0,0><<<dim3(G3 / 64, (BB * (TT - 1) + 63) / 64), 256>>>(p_demb, Wi_d, bi_d, p_gid,
                                                                   BB * (TT - 1), G3, EE);

    // 5) decoder recurrence (persistent, 2 barriers/step, fused gates+attention)
    dec_persist<<<128, 256, DEC_SMEM>>>(p_whpd, bh_d, p_gid, Wq, bq, p_K, p_V,
                                        p_hdec, p_hid, p_pgh);

    // 6) output head: X = gelu(hid @ W1 + b1) -> fp16 directly, then HMMA vs W2
    gemm_k<1,1><<<dim3(DD / 64, (BB * (TT - 1) + 63) / 64), 256>>>(p_hid, W1, b1, xh,
                                                                   BB * (TT - 1), DD, DD);
    head_mma<<<dim3((MROWS + 127) / 128, VOC / 128), 256>>>(xh, w2h, b2, out);
}